// round 9
// baseline (speedup 1.0000x reference)
#include <cuda_runtime.h>
#include <cuda_bf16.h>
#include <cstdint>

#define NTOK 32768
#define DDIM 256
#define KC   1024
#define HW   1024
#define DECAY_F 0.99f
#define ONE_M_DECAY 0.01f
#define EPS_F 1e-5f

// output offsets (concatenated float32 outputs in reference return order)
#define O_ZQ   0
#define O_IDX  8388608
#define O_LOSS 8421376
#define O_EMB  8421377
#define O_CS   8683521
#define O_EAVG 8684545

__device__ float g_cs[KC];
__device__ int   g_idx[NTOK];
__device__ float g_enorm[KC];
__device__ float g_partial[1024];    // per-block Σ||x||^2 (split_x)
__device__ float g_partial2[256];    // per-CTA Σ best (dist)
__device__ float g_n;
__device__ int   g_off[KC], g_cur[KC], g_cnt[KC];
__device__ int   g_toklist[NTOK];
__device__ float g_flat[NTOK * DDIM];   // fp32 tokens x dims (transposed z)

// A splits in mma-FRAGMENT-MAJOR layout: u32 idx = tblk16*2048 + ks*128 + lane*4 + frag
__device__ __align__(16) uint32_t g_ax0f[NTOK * 128];
__device__ __align__(16) uint32_t g_ax1f[NTOK * 128];
__device__ __align__(16) uint32_t g_ax2f[NTOK * 128];
// B splits row-major (code-major, 512B rows)
__device__ __align__(16) __nv_bfloat16 g_be0[KC * DDIM];
__device__ __align__(16) __nv_bfloat16 g_be1[KC * DDIM];
__device__ __align__(16) __nv_bfloat16 g_be2[KC * DDIM];

__device__ __forceinline__ uint32_t smem_u32(const void* p) {
    uint32_t a;
    asm("{ .reg .u64 t; cvta.to.shared.u64 t, %1; cvt.u32.u64 %0, t; }"
        : "=r"(a) : "l"(p));
    return a;
}

__device__ __forceinline__ void mma16816(float* c, const uint32_t* a,
                                         uint32_t b0, uint32_t b1) {
    asm volatile(
        "mma.sync.aligned.m16n8k16.row.col.f32.bf16.bf16.f32 "
        "{%0,%1,%2,%3}, {%4,%5,%6,%7}, {%8,%9}, {%0,%1,%2,%3};"
        : "+f"(c[0]), "+f"(c[1]), "+f"(c[2]), "+f"(c[3])
        : "r"(a[0]), "r"(a[1]), "r"(a[2]), "r"(a[3]), "r"(b0), "r"(b1));
}

#define LDSM_X4(r0, r1, r2, r3, addr) \
    asm volatile("ldmatrix.sync.aligned.m8n8.x4.shared.b16 {%0,%1,%2,%3}, [%4];" \
        : "=r"(r0), "=r"(r1), "=r"(r2), "=r"(r3) : "r"(addr))

#define CP_ASYNC16(dst, src) \
    asm volatile("cp.async.cg.shared.global [%0], [%1], 16;" \
                 :: "r"(dst), "l"(src) : "memory")
#define CP_COMMIT() asm volatile("cp.async.commit_group;" ::: "memory")

__device__ __forceinline__ void split3(float v, __nv_bfloat16& h,
                                       __nv_bfloat16& m, __nv_bfloat16& l) {
    h = __float2bfloat16_rn(v);
    float r = v - __bfloat162float(h);
    m = __float2bfloat16_rn(r);
    float r2 = r - __bfloat162float(m);
    l = __float2bfloat16_rn(r2);
}

// ---------------------------------------------------------------------------
// Fused e-split + ||e||^2
// ---------------------------------------------------------------------------
__global__ __launch_bounds__(256) void split_e_enorm_kernel(const float* __restrict__ embed) {
    __shared__ float wsum[8];
    int c = blockIdx.x, tid = threadIdx.x;
    int i = c * DDIM + tid;
    float v = embed[i];
    __nv_bfloat16 h, m, l;
    split3(v, h, m, l);
    g_be0[i] = h; g_be1[i] = m; g_be2[i] = l;
    float s = v * v;
#pragma unroll
    for (int off = 16; off; off >>= 1) s += __shfl_xor_sync(0xffffffffu, s, off);
    if ((tid & 31) == 0) wsum[tid >> 5] = s;
    __syncthreads();
    if (tid == 0) {
        float t = 0.f;
#pragma unroll
        for (int w = 0; w < 8; w++) t += wsum[w];
        g_enorm[c] = t;
    }
}

// token-transpose + split + fragment-major pack + fp32 flat copy + ||x||^2
__global__ __launch_bounds__(256) void split_x_kernel(const float* __restrict__ z) {
    __shared__ float s[32][257];
    __shared__ float wsum[8];
    int tid = threadIdx.x;
    int t0 = blockIdx.x * 32;
    int bimg = t0 >> 10, hw0 = t0 & 1023;
    int d0 = tid >> 5, ti = tid & 31;
#pragma unroll
    for (int mrow = 0; mrow < 32; mrow++) {
        int d = mrow * 8 + d0;
        s[ti][d] = z[((size_t)bimg * DDIM + d) * HW + hw0 + ti];
    }
    __syncthreads();
    // fp32 flat copy + xnorm partial
    float xn = 0.f;
#pragma unroll
    for (int l = 0; l < 32; l++) {
        float v = s[l][tid];
        g_flat[(size_t)(t0 + l) * DDIM + tid] = v;
        xn += v * v;
    }
#pragma unroll
    for (int off = 16; off; off >>= 1) xn += __shfl_xor_sync(0xffffffffu, xn, off);
    if ((tid & 31) == 0) wsum[tid >> 5] = xn;
    // fragment-major bf16 splits
    size_t obase = (size_t)(t0 >> 4) * 2048;
#pragma unroll
    for (int i = 0; i < 16; i++) {
        int j = i * 256 + tid;
        int tbl = j >> 11, r = j & 2047;
        int ks = r >> 7, L = (r >> 2) & 31, f = r & 3;
        int g = L >> 2, q = L & 3, half = f & 1, kh = f >> 1;
        int tl = tbl * 16 + half * 8 + g;
        int d = ks * 16 + kh * 8 + q * 2;
        float v0 = s[tl][d], v1 = s[tl][d + 1];
        __nv_bfloat16 h0, m0, l0, h1, m1, l1;
        split3(v0, h0, m0, l0);
        split3(v1, h1, m1, l1);
        g_ax0f[obase + j] = ((uint32_t)__bfloat16_as_ushort(h1) << 16) | __bfloat16_as_ushort(h0);
        g_ax1f[obase + j] = ((uint32_t)__bfloat16_as_ushort(m1) << 16) | __bfloat16_as_ushort(m0);
        g_ax2f[obase + j] = ((uint32_t)__bfloat16_as_ushort(l1) << 16) | __bfloat16_as_ushort(l0);
    }
    __syncthreads();
    if (tid == 0) {
        float t = 0.f;
#pragma unroll
        for (int w = 0; w < 8; w++) t += wsum[w];
        g_partial[blockIdx.x] = t;
    }
}

// ---------------------------------------------------------------------------
// Distance + argmin (unchanged core, R7-verified 240us) + per-CTA best-sum
// ---------------------------------------------------------------------------
#define BUF_BYTES 98304
#define SMEM_TOTAL (4096 + BUF_BYTES)

__global__ __launch_bounds__(128, 2) void dist_hmma_kernel(float* __restrict__ out)
{
    extern __shared__ __align__(1024) char smem[];
    __shared__ float wbs[4];
    float* s_enorm = (float*)smem;
    uint32_t sb = smem_u32(smem);
    int tid = threadIdx.x, wid = tid >> 5, lane = tid & 31;
    int t0 = blockIdx.x * 128;
    int group = lane >> 2, tq = lane & 3;
    int bn = (lane & 7) + ((lane >> 4) << 3);
    int bkh = (lane >> 3) & 1;

#pragma unroll
    for (int i = 0; i < 8; i++) s_enorm[i * 128 + tid] = g_enorm[i * 128 + tid];

    size_t abase[2];
#pragma unroll
    for (int mt = 0; mt < 2; mt++)
        abase[mt] = (size_t)(blockIdx.x * 8 + wid * 2 + mt) * 2048 + lane * 4;

    float best[4];
    int   bestk[4];
#pragma unroll
    for (int i = 0; i < 4; i++) { best[i] = 3.4e38f; bestk[i] = 0; }

    const char* bsrc[3] = {(const char*)g_be0, (const char*)g_be1, (const char*)g_be2};

#pragma unroll
    for (int it = 0; it < 48; it++) {
        int id = it * 128 + tid;
        int s = id >> 11, rem = id & 2047, n = rem >> 5, col = rem & 31;
        uint32_t dst = sb + 4096 + s * 32768 + n * 512 + ((col ^ (n & 7)) << 4);
        CP_ASYNC16(dst, bsrc[s] + (size_t)n * 512 + col * 16);
    }
    CP_COMMIT();

#pragma unroll 1
    for (int nc = 0; nc < 16; nc++) {
        asm volatile("cp.async.wait_group 0;" ::: "memory");
        __syncthreads();

        uint32_t bbase = sb + 4096;
        float acc[4][2][8];
#pragma unroll
        for (int nt = 0; nt < 4; nt++)
#pragma unroll
            for (int mt = 0; mt < 2; mt++)
#pragma unroll
                for (int j = 0; j < 8; j++) acc[nt][mt][j] = 0.f;

        uint4 acur[3][2], anxt[3][2];
#pragma unroll
        for (int mt = 0; mt < 2; mt++) {
            acur[0][mt] = *(const uint4*)(g_ax0f + abase[mt]);
            acur[1][mt] = *(const uint4*)(g_ax1f + abase[mt]);
            acur[2][mt] = *(const uint4*)(g_ax2f + abase[mt]);
        }

#pragma unroll 1
        for (int ks = 0; ks < 16; ks++) {
            if (ks < 15) {
#pragma unroll
                for (int mt = 0; mt < 2; mt++) {
                    size_t o = abase[mt] + (ks + 1) * 128;
                    anxt[0][mt] = *(const uint4*)(g_ax0f + o);
                    anxt[1][mt] = *(const uint4*)(g_ax1f + o);
                    anxt[2][mt] = *(const uint4*)(g_ax2f + o);
                }
            }
#pragma unroll
            for (int nt = 0; nt < 4; nt++) {
                int nl = nt * 16 + bn;
                uint32_t baddr = bbase + nl * 512 + (((ks * 2 + bkh) ^ (nl & 7)) << 4);
                uint32_t b[3][4];
                LDSM_X4(b[0][0], b[0][1], b[0][2], b[0][3], baddr);
                LDSM_X4(b[1][0], b[1][1], b[1][2], b[1][3], baddr + 32768);
                LDSM_X4(b[2][0], b[2][1], b[2][2], b[2][3], baddr + 65536);
#pragma unroll
                for (int mt = 0; mt < 2; mt++) {
                    const uint32_t* a0 = (const uint32_t*)&acur[0][mt];
                    const uint32_t* a1 = (const uint32_t*)&acur[1][mt];
                    const uint32_t* a2 = (const uint32_t*)&acur[2][mt];
                    float* c0 = acc[nt][mt];
                    float* c1 = acc[nt][mt] + 4;
                    mma16816(c0, a0, b[0][0], b[0][1]);
                    mma16816(c1, a0, b[0][2], b[0][3]);
                    mma16816(c0, a0, b[1][0], b[1][1]);
                    mma16816(c1, a0, b[1][2], b[1][3]);
                    mma16816(c0, a1, b[0][0], b[0][1]);
                    mma16816(c1, a1, b[0][2], b[0][3]);
                    mma16816(c0, a1, b[1][0], b[1][1]);
                    mma16816(c1, a1, b[1][2], b[1][3]);
                    mma16816(c0, a2, b[0][0], b[0][1]);
                    mma16816(c1, a2, b[0][2], b[0][3]);
                    mma16816(c0, a0, b[2][0], b[2][1]);
                    mma16816(c1, a0, b[2][2], b[2][3]);
                }
            }
#pragma unroll
            for (int s = 0; s < 3; s++)
#pragma unroll
                for (int mt = 0; mt < 2; mt++) acur[s][mt] = anxt[s][mt];
        }
        int n0 = nc * 64;
#pragma unroll
        for (int nt = 0; nt < 4; nt++)
#pragma unroll
            for (int mt = 0; mt < 2; mt++)
#pragma unroll
                for (int nh = 0; nh < 2; nh++) {
                    int cb = n0 + nt * 16 + nh * 8 + tq * 2;
                    float2 en = *(const float2*)&s_enorm[cb];
                    float* c = &acc[nt][mt][nh * 4];
                    float d0 = en.x - 2.f * c[0];
                    float d1 = en.y - 2.f * c[1];
                    float d2 = en.x - 2.f * c[2];
                    float d3 = en.y - 2.f * c[3];
                    int bi = mt * 2;
                    if (d0 < best[bi]) { best[bi] = d0; bestk[bi] = cb; }
                    if (d1 < best[bi]) { best[bi] = d1; bestk[bi] = cb + 1; }
                    if (d2 < best[bi + 1]) { best[bi + 1] = d2; bestk[bi + 1] = cb; }
                    if (d3 < best[bi + 1]) { best[bi + 1] = d3; bestk[bi + 1] = cb + 1; }
                }
        __syncthreads();
        if (nc < 15) {
            int n0n = (nc + 1) * 64;
#pragma unroll
            for (int it = 0; it < 48; it++) {
                int id = it * 128 + tid;
                int s = id >> 11, rem = id & 2047, n = rem >> 5, col = rem & 31;
                uint32_t dst = sb + 4096 + s * 32768 + n * 512 + ((col ^ (n & 7)) << 4);
                CP_ASYNC16(dst, bsrc[s] + (size_t)(n0n + n) * 512 + col * 16);
            }
            CP_COMMIT();
        }
    }

    // quad reduce
#pragma unroll
    for (int off = 1; off <= 2; off <<= 1)
#pragma unroll
        for (int i = 0; i < 4; i++) {
            float ov = __shfl_xor_sync(0xffffffffu, best[i], off);
            int   ok = __shfl_xor_sync(0xffffffffu, bestk[i], off);
            if (ov < best[i] || (ov == best[i] && ok < bestk[i])) {
                best[i] = ov; bestk[i] = ok;
            }
        }
    if ((lane & 3) == 0) {
#pragma unroll
        for (int mt = 0; mt < 2; mt++)
#pragma unroll
            for (int h = 0; h < 2; h++) {
                int t = t0 + wid * 32 + mt * 16 + h * 8 + group;
                int bk = bestk[mt * 2 + h];
                g_idx[t] = bk;
                out[O_IDX + t] = (float)bk;
                atomicAdd(&g_cs[bk], 1.0f);
            }
    }
    // per-CTA sum of best distances (for the loss identity)
    float bs = best[0] + best[1] + best[2] + best[3];
#pragma unroll
    for (int off = 16; off; off >>= 1) bs += __shfl_xor_sync(0xffffffffu, bs, off);
    bs *= 0.25f;   // each quad's value counted 4x
    if (lane == 0) wbs[wid] = bs;
    __syncthreads();
    if (tid == 0) g_partial2[blockIdx.x] = wbs[0] + wbs[1] + wbs[2] + wbs[3];
}

// ---------------------------------------------------------------------------
// prefix-scan of counts -> offsets/cursors
// ---------------------------------------------------------------------------
__global__ void prefix_kernel() {
    __shared__ int sc[KC];
    int k = threadIdx.x;
    int c = (int)(g_cs[k] + 0.5f);
    sc[k] = c;
    __syncthreads();
    for (int off = 1; off < KC; off <<= 1) {
        int v = (k >= off) ? sc[k - off] : 0;
        __syncthreads();
        sc[k] += v;
        __syncthreads();
    }
    int excl = sc[k] - c;
    g_off[k] = excl; g_cur[k] = excl; g_cnt[k] = c;
}

__global__ void scatter_kernel() {
    int t = blockIdx.x * 256 + threadIdx.x;
    int k = g_idx[t];
    int s = atomicAdd(&g_cur[k], 1);
    g_toklist[s] = t;
}

// ---------------------------------------------------------------------------
// Gather z_q only: embed row gather -> strided (B,D,H,W) write. No atomics.
// ---------------------------------------------------------------------------
__global__ __launch_bounds__(256) void gather_kernel(
    const float* __restrict__ embed, float* __restrict__ out)
{
    __shared__ float s2[DDIM][33];
    __shared__ int   kidx[32];
    int tid = threadIdx.x;
    int t0 = blockIdx.x * 32;
    int bimg = t0 >> 10, hw0 = t0 & 1023;

    if (tid < 32) kidx[tid] = g_idx[t0 + tid];
    __syncthreads();
#pragma unroll
    for (int l = 0; l < 32; l++)
        s2[tid][l] = embed[(size_t)kidx[l] * DDIM + tid];   // coalesced rows
    __syncthreads();

    int ti = tid & 31, dq = (tid >> 5) * 4;
    float* ob = out + O_ZQ + (size_t)bimg * DDIM * HW + hw0 + ti;
#pragma unroll
    for (int m = 0; m < 8; m++) {
        int d = m * 32 + dq;
        size_t zo = (size_t)d * HW;
        ob[zo] = s2[d][ti];
        ob[zo + HW] = s2[d + 1][ti];
        ob[zo + 2 * HW] = s2[d + 2][ti];
        ob[zo + 3 * HW] = s2[d + 3][ti];
    }
}

// loss finalize + EMA cluster-size + n (single block)
__global__ void ema_a_kernel(const float* __restrict__ cluster_size,
                             float* __restrict__ out) {
    __shared__ float red[KC];
    int k = threadIdx.x;
    float ncs = cluster_size[k] * DECAY_F + ONE_M_DECAY * g_cs[k];
    out[O_CS + k] = ncs;
    red[k] = ncs;
    __syncthreads();
    for (int off = 512; off; off >>= 1) {
        if (k < off) red[k] += red[k + off];
        __syncthreads();
    }
    if (k == 0) g_n = red[0];
    __syncthreads();
    red[k] = g_partial[k] + (k < 256 ? g_partial2[k] : 0.f);
    __syncthreads();
    for (int off = 512; off; off >>= 1) {
        if (k < off) red[k] += red[k + off];
        __syncthreads();
    }
    if (k == 0) out[O_LOSS] = red[0] / 8388608.0f;
}

// ---------------------------------------------------------------------------
// Segment-sum per code (no atomics) + EMA embed_avg + new embed
// ---------------------------------------------------------------------------
__global__ __launch_bounds__(256) void es_kernel(
    const float* __restrict__ cluster_size, const float* __restrict__ embed_avg,
    float* __restrict__ out)
{
    __shared__ int tl[256];
    int k = blockIdx.x, tid = threadIdx.x;
    int off = g_off[k], cnt = g_cnt[k];
    float acc = 0.f;
    for (int base = 0; base < cnt; base += 256) {
        int m = min(256, cnt - base);
        if (tid < m) tl[tid] = g_toklist[off + base + tid];
        __syncthreads();
        for (int j = 0; j < m; j++)
            acc += g_flat[(size_t)tl[j] * DDIM + tid];
        __syncthreads();
    }
    int i = k * DDIM + tid;
    float nea = embed_avg[i] * DECAY_F + ONE_M_DECAY * acc;
    out[O_EAVG + i] = nea;
    float ncs = cluster_size[k] * DECAY_F + ONE_M_DECAY * (float)cnt;
    float n = g_n;
    float csn = (ncs + EPS_F) / (n + KC * EPS_F) * n;
    out[O_EMB + i] = nea / csn;
}

// ---------------------------------------------------------------------------
extern "C" void kernel_launch(void* const* d_in, const int* in_sizes, int n_in,
                              void* d_out, int out_size)
{
    const float* z            = (const float*)d_in[0];
    const float* embed        = (const float*)d_in[1];
    const float* cluster_size = (const float*)d_in[2];
    const float* embed_avg    = (const float*)d_in[3];
    float* out = (float*)d_out;

    cudaFuncSetAttribute(dist_hmma_kernel,
                         cudaFuncAttributeMaxDynamicSharedMemorySize, SMEM_TOTAL);

    void* p;
    cudaGetSymbolAddress(&p, g_cs);
    cudaMemsetAsync(p, 0, KC * sizeof(float));               // launch 1

    split_e_enorm_kernel<<<KC, 256>>>(embed);                // launch 2
    split_x_kernel<<<NTOK / 32, 256>>>(z);                   // launch 3
    dist_hmma_kernel<<<NTOK / 128, 128, SMEM_TOTAL>>>(out);  // launch 4
    prefix_kernel<<<1, KC>>>();                              // launch 5
    gather_kernel<<<NTOK / 32, 256>>>(embed, out);           // launch 6 <- ncu
    scatter_kernel<<<NTOK / 256, 256>>>();                   // launch 7
    ema_a_kernel<<<1, KC>>>(cluster_size, out);              // launch 8
    es_kernel<<<KC, 256>>>(cluster_size, embed_avg, out);    // launch 9
}

// round 10
// speedup vs baseline: 1.2261x; 1.2261x over previous
#include <cuda_runtime.h>
#include <cuda_bf16.h>
#include <cstdint>

#define NTOK 32768
#define DDIM 256
#define KC   1024
#define HW   1024
#define DECAY_F 0.99f
#define ONE_M_DECAY 0.01f
#define EPS_F 1e-5f

// output offsets (concatenated float32 outputs in reference return order)
#define O_ZQ   0
#define O_IDX  8388608
#define O_LOSS 8421376
#define O_EMB  8421377
#define O_CS   8683521
#define O_EAVG 8684545

__device__ float g_es[KC * DDIM];
__device__ float g_cs[KC];
__device__ int   g_idx[NTOK];
__device__ float g_enorm[KC];
__device__ float g_partial[1024];
__device__ float g_n;

// A splits in mma-FRAGMENT-MAJOR layout: u32 idx = tblk16*2048 + ks*128 + lane*4 + frag
__device__ __align__(16) uint32_t g_ax0f[NTOK * 128];
__device__ __align__(16) uint32_t g_ax1f[NTOK * 128];
__device__ __align__(16) uint32_t g_ax2f[NTOK * 128];
// B splits row-major (code-major, 512B rows)
__device__ __align__(16) __nv_bfloat16 g_be0[KC * DDIM];
__device__ __align__(16) __nv_bfloat16 g_be1[KC * DDIM];
__device__ __align__(16) __nv_bfloat16 g_be2[KC * DDIM];

__device__ __forceinline__ uint32_t smem_u32(const void* p) {
    uint32_t a;
    asm("{ .reg .u64 t; cvta.to.shared.u64 t, %1; cvt.u32.u64 %0, t; }"
        : "=r"(a) : "l"(p));
    return a;
}

__device__ __forceinline__ void mma16816(float* c, const uint32_t* a,
                                         uint32_t b0, uint32_t b1) {
    asm volatile(
        "mma.sync.aligned.m16n8k16.row.col.f32.bf16.bf16.f32 "
        "{%0,%1,%2,%3}, {%4,%5,%6,%7}, {%8,%9}, {%0,%1,%2,%3};"
        : "+f"(c[0]), "+f"(c[1]), "+f"(c[2]), "+f"(c[3])
        : "r"(a[0]), "r"(a[1]), "r"(a[2]), "r"(a[3]), "r"(b0), "r"(b1));
}

#define LDSM_X4(r0, r1, r2, r3, addr) \
    asm volatile("ldmatrix.sync.aligned.m8n8.x4.shared.b16 {%0,%1,%2,%3}, [%4];" \
        : "=r"(r0), "=r"(r1), "=r"(r2), "=r"(r3) : "r"(addr))

#define CP_ASYNC16(dst, src) \
    asm volatile("cp.async.cg.shared.global [%0], [%1], 16;" \
                 :: "r"(dst), "l"(src) : "memory")
#define CP_COMMIT() asm volatile("cp.async.commit_group;" ::: "memory")

__device__ __forceinline__ void split3(float v, __nv_bfloat16& h,
                                       __nv_bfloat16& m, __nv_bfloat16& l) {
    h = __float2bfloat16_rn(v);
    float r = v - __bfloat162float(h);
    m = __float2bfloat16_rn(r);
    float r2 = r - __bfloat162float(m);
    l = __float2bfloat16_rn(r2);
}

__global__ void pre_kernel() { if (threadIdx.x == 0) g_n = 0.f; }

// ---------------------------------------------------------------------------
// Fused e-split + ||e||^2
// ---------------------------------------------------------------------------
__global__ __launch_bounds__(256) void split_e_enorm_kernel(const float* __restrict__ embed) {
    __shared__ float wsum[8];
    int c = blockIdx.x, tid = threadIdx.x;
    int i = c * DDIM + tid;
    float v = embed[i];
    __nv_bfloat16 h, m, l;
    split3(v, h, m, l);
    g_be0[i] = h; g_be1[i] = m; g_be2[i] = l;
    float s = v * v;
#pragma unroll
    for (int off = 16; off; off >>= 1) s += __shfl_xor_sync(0xffffffffu, s, off);
    if ((tid & 31) == 0) wsum[tid >> 5] = s;
    __syncthreads();
    if (tid == 0) {
        float t = 0.f;
#pragma unroll
        for (int w = 0; w < 8; w++) t += wsum[w];
        g_enorm[c] = t;
    }
}

// token-transpose + split + fragment-major pack
__global__ __launch_bounds__(256) void split_x_kernel(const float* __restrict__ z) {
    __shared__ float s[32][257];
    int tid = threadIdx.x;
    int t0 = blockIdx.x * 32;
    int bimg = t0 >> 10, hw0 = t0 & 1023;
    int d0 = tid >> 5, ti = tid & 31;
#pragma unroll
    for (int mrow = 0; mrow < 32; mrow++) {
        int d = mrow * 8 + d0;
        s[ti][d] = z[((size_t)bimg * DDIM + d) * HW + hw0 + ti];
    }
    __syncthreads();
    size_t obase = (size_t)(t0 >> 4) * 2048;
#pragma unroll
    for (int i = 0; i < 16; i++) {
        int j = i * 256 + tid;
        int tbl = j >> 11, r = j & 2047;
        int ks = r >> 7, L = (r >> 2) & 31, f = r & 3;
        int g = L >> 2, q = L & 3, half = f & 1, kh = f >> 1;
        int tl = tbl * 16 + half * 8 + g;
        int d = ks * 16 + kh * 8 + q * 2;
        float v0 = s[tl][d], v1 = s[tl][d + 1];
        __nv_bfloat16 h0, m0, l0, h1, m1, l1;
        split3(v0, h0, m0, l0);
        split3(v1, h1, m1, l1);
        g_ax0f[obase + j] = ((uint32_t)__bfloat16_as_ushort(h1) << 16) | __bfloat16_as_ushort(h0);
        g_ax1f[obase + j] = ((uint32_t)__bfloat16_as_ushort(m1) << 16) | __bfloat16_as_ushort(m0);
        g_ax2f[obase + j] = ((uint32_t)__bfloat16_as_ushort(l1) << 16) | __bfloat16_as_ushort(l0);
    }
}

// ---------------------------------------------------------------------------
// Distance + argmin: warp-MMA bf16x6 emulated fp32.
// Grid 256 x 128 thr, 2 CTAs/SM (100KB smem) -> all 148 SMs busy.
// CTA = 128 tokens (4 warps x m32) x 1024 codes in 16 n-chunks of 64.
// B single-buffered 96KB; next-chunk cp.async issued BEFORE the argmin
// fold so copy flight time overlaps the fold. A via register dbl-buffer.
// ---------------------------------------------------------------------------
#define BUF_BYTES 98304
#define SMEM_TOTAL (4096 + BUF_BYTES)

__global__ __launch_bounds__(128, 2) void dist_hmma_kernel(float* __restrict__ out)
{
    extern __shared__ __align__(1024) char smem[];
    float* s_enorm = (float*)smem;
    uint32_t sb = smem_u32(smem);
    int tid = threadIdx.x, wid = tid >> 5, lane = tid & 31;
    int t0 = blockIdx.x * 128;
    int group = lane >> 2, tq = lane & 3;
    int bn = (lane & 7) + ((lane >> 4) << 3);
    int bkh = (lane >> 3) & 1;

#pragma unroll
    for (int i = 0; i < 8; i++) s_enorm[i * 128 + tid] = g_enorm[i * 128 + tid];

    size_t abase[2];
#pragma unroll
    for (int mt = 0; mt < 2; mt++)
        abase[mt] = (size_t)(blockIdx.x * 8 + wid * 2 + mt) * 2048 + lane * 4;

    float best[4];
    int   bestk[4];
#pragma unroll
    for (int i = 0; i < 4; i++) { best[i] = 3.4e38f; bestk[i] = 0; }

    const char* bsrc[3] = {(const char*)g_be0, (const char*)g_be1, (const char*)g_be2};

    // ---- stage chunk 0: 3 splits x 64 codes x 512B = 96KB ----
#pragma unroll
    for (int it = 0; it < 48; it++) {
        int id = it * 128 + tid;
        int s = id >> 11, rem = id & 2047, n = rem >> 5, col = rem & 31;
        uint32_t dst = sb + 4096 + s * 32768 + n * 512 + ((col ^ (n & 7)) << 4);
        CP_ASYNC16(dst, bsrc[s] + (size_t)n * 512 + col * 16);
    }
    CP_COMMIT();

#pragma unroll 1
    for (int nc = 0; nc < 16; nc++) {
        asm volatile("cp.async.wait_group 0;" ::: "memory");
        __syncthreads();

        uint32_t bbase = sb + 4096;
        float acc[4][2][8];
#pragma unroll
        for (int nt = 0; nt < 4; nt++)
#pragma unroll
            for (int mt = 0; mt < 2; mt++)
#pragma unroll
                for (int j = 0; j < 8; j++) acc[nt][mt][j] = 0.f;

        uint4 acur[3][2], anxt[3][2];
#pragma unroll
        for (int mt = 0; mt < 2; mt++) {
            acur[0][mt] = *(const uint4*)(g_ax0f + abase[mt]);
            acur[1][mt] = *(const uint4*)(g_ax1f + abase[mt]);
            acur[2][mt] = *(const uint4*)(g_ax2f + abase[mt]);
        }

#pragma unroll 1
        for (int ks = 0; ks < 16; ks++) {
            if (ks < 15) {
#pragma unroll
                for (int mt = 0; mt < 2; mt++) {
                    size_t o = abase[mt] + (ks + 1) * 128;
                    anxt[0][mt] = *(const uint4*)(g_ax0f + o);
                    anxt[1][mt] = *(const uint4*)(g_ax1f + o);
                    anxt[2][mt] = *(const uint4*)(g_ax2f + o);
                }
            }
#pragma unroll
            for (int nt = 0; nt < 4; nt++) {
                int nl = nt * 16 + bn;
                uint32_t baddr = bbase + nl * 512 + (((ks * 2 + bkh) ^ (nl & 7)) << 4);
                uint32_t b[3][4];
                LDSM_X4(b[0][0], b[0][1], b[0][2], b[0][3], baddr);
                LDSM_X4(b[1][0], b[1][1], b[1][2], b[1][3], baddr + 32768);
                LDSM_X4(b[2][0], b[2][1], b[2][2], b[2][3], baddr + 65536);
#pragma unroll
                for (int mt = 0; mt < 2; mt++) {
                    const uint32_t* a0 = (const uint32_t*)&acur[0][mt];
                    const uint32_t* a1 = (const uint32_t*)&acur[1][mt];
                    const uint32_t* a2 = (const uint32_t*)&acur[2][mt];
                    float* c0 = acc[nt][mt];
                    float* c1 = acc[nt][mt] + 4;
                    // 6 split-terms: hh, hm, mh, mm, lh, hl
                    mma16816(c0, a0, b[0][0], b[0][1]);
                    mma16816(c1, a0, b[0][2], b[0][3]);
                    mma16816(c0, a0, b[1][0], b[1][1]);
                    mma16816(c1, a0, b[1][2], b[1][3]);
                    mma16816(c0, a1, b[0][0], b[0][1]);
                    mma16816(c1, a1, b[0][2], b[0][3]);
                    mma16816(c0, a1, b[1][0], b[1][1]);
                    mma16816(c1, a1, b[1][2], b[1][3]);
                    mma16816(c0, a2, b[0][0], b[0][1]);
                    mma16816(c1, a2, b[0][2], b[0][3]);
                    mma16816(c0, a0, b[2][0], b[2][1]);
                    mma16816(c1, a0, b[2][2], b[2][3]);
                }
            }
#pragma unroll
            for (int s = 0; s < 3; s++)
#pragma unroll
                for (int mt = 0; mt < 2; mt++) acur[s][mt] = anxt[s][mt];
        }

        // all warps done reading B -> start next-chunk staging NOW,
        // then do the argmin fold while the copy is in flight
        __syncthreads();
        if (nc < 15) {
            int n0n = (nc + 1) * 64;
#pragma unroll
            for (int it = 0; it < 48; it++) {
                int id = it * 128 + tid;
                int s = id >> 11, rem = id & 2047, n = rem >> 5, col = rem & 31;
                uint32_t dst = sb + 4096 + s * 32768 + n * 512 + ((col ^ (n & 7)) << 4);
                CP_ASYNC16(dst, bsrc[s] + (size_t)(n0n + n) * 512 + col * 16);
            }
            CP_COMMIT();
        }

        // ---- fold argmin: dist = ||e||^2 - 2 acc ----
        int n0 = nc * 64;
#pragma unroll
        for (int nt = 0; nt < 4; nt++)
#pragma unroll
            for (int mt = 0; mt < 2; mt++)
#pragma unroll
                for (int nh = 0; nh < 2; nh++) {
                    int cb = n0 + nt * 16 + nh * 8 + tq * 2;
                    float2 en = *(const float2*)&s_enorm[cb];
                    float* c = &acc[nt][mt][nh * 4];
                    float d0 = en.x - 2.f * c[0];
                    float d1 = en.y - 2.f * c[1];
                    float d2 = en.x - 2.f * c[2];
                    float d3 = en.y - 2.f * c[3];
                    int bi = mt * 2;
                    if (d0 < best[bi]) { best[bi] = d0; bestk[bi] = cb; }
                    if (d1 < best[bi]) { best[bi] = d1; bestk[bi] = cb + 1; }
                    if (d2 < best[bi + 1]) { best[bi + 1] = d2; bestk[bi + 1] = cb; }
                    if (d3 < best[bi + 1]) { best[bi + 1] = d3; bestk[bi + 1] = cb + 1; }
                }
    }

    // quad reduce (lanes in a quad share token rows)
#pragma unroll
    for (int off = 1; off <= 2; off <<= 1)
#pragma unroll
        for (int i = 0; i < 4; i++) {
            float ov = __shfl_xor_sync(0xffffffffu, best[i], off);
            int   ok = __shfl_xor_sync(0xffffffffu, bestk[i], off);
            if (ov < best[i] || (ov == best[i] && ok < bestk[i])) {
                best[i] = ov; bestk[i] = ok;
            }
        }
    if ((lane & 3) == 0) {
#pragma unroll
        for (int mt = 0; mt < 2; mt++)
#pragma unroll
            for (int h = 0; h < 2; h++) {
                int t = t0 + wid * 32 + mt * 16 + h * 8 + group;
                int bk = bestk[mt * 2 + h];
                g_idx[t] = bk;
                out[O_IDX + t] = (float)bk;
                atomicAdd(&g_cs[bk], 1.0f);
            }
    }
}

// ---------------------------------------------------------------------------
// Gather z_q, vq_loss partials, es segment-sum (v4 atomics, shuffle reduce)
// ---------------------------------------------------------------------------
__global__ __launch_bounds__(256) void gather_kernel(
    const float* __restrict__ z, const float* __restrict__ embed,
    float* __restrict__ out)
{
    __shared__ float s2[DDIM][33];
    __shared__ int   kidx[32];
    __shared__ float wred[8];
    int tid = threadIdx.x;
    int t0 = blockIdx.x * 32;
    int bimg = t0 >> 10, hw0 = t0 & 1023;

    if (tid < 32) kidx[tid] = g_idx[t0 + tid];
    __syncthreads();
#pragma unroll
    for (int l = 0; l < 32; l++)
        s2[tid][l] = embed[(size_t)kidx[l] * DDIM + tid];   // coalesced rows
    __syncthreads();

    int ti = tid & 31, dq = (tid >> 5) * 4;
    int myk = kidx[ti];
    float* esrow = &g_es[(size_t)myk * DDIM];
    float lsum = 0.f;
    const float* zb = z + (size_t)bimg * DDIM * HW + hw0 + ti;
    float* ob = out + O_ZQ + (size_t)bimg * DDIM * HW + hw0 + ti;
#pragma unroll
    for (int m = 0; m < 8; m++) {
        int d = m * 32 + dq;
        float e0 = s2[d][ti], e1 = s2[d + 1][ti], e2 = s2[d + 2][ti], e3 = s2[d + 3][ti];
        size_t zo = (size_t)d * HW;
        float z0 = zb[zo], z1 = zb[zo + HW], z2 = zb[zo + 2 * HW], z3 = zb[zo + 3 * HW];
        ob[zo] = e0; ob[zo + HW] = e1; ob[zo + 2 * HW] = e2; ob[zo + 3 * HW] = e3;
        float f0 = z0 - e0, f1 = z1 - e1, f2 = z2 - e2, f3 = z3 - e3;
        lsum += f0 * f0 + f1 * f1 + f2 * f2 + f3 * f3;
        asm volatile("red.global.add.v4.f32 [%0], {%1, %2, %3, %4};"
                     :: "l"(esrow + d), "f"(z0), "f"(z1), "f"(z2), "f"(z3) : "memory");
    }
#pragma unroll
    for (int off = 16; off; off >>= 1) lsum += __shfl_xor_sync(0xffffffffu, lsum, off);
    if ((tid & 31) == 0) wred[tid >> 5] = lsum;
    __syncthreads();
    if (tid == 0) {
        float s = 0.f;
#pragma unroll
        for (int w = 0; w < 8; w++) s += wred[w];
        g_partial[blockIdx.x] = s;
    }
}

// loss finalize + EMA cluster-size + n (single block, clean)
__global__ void ema_a_kernel(const float* __restrict__ cluster_size,
                             float* __restrict__ out) {
    __shared__ float red[KC];
    __shared__ float red2[KC];
    int k = threadIdx.x;
    float ncs = cluster_size[k] * DECAY_F + ONE_M_DECAY * g_cs[k];
    out[O_CS + k] = ncs;
    red[k] = ncs;
    red2[k] = g_partial[k];
    __syncthreads();
    for (int off = 512; off; off >>= 1) {
        if (k < off) { red[k] += red[k + off]; red2[k] += red2[k + off]; }
        __syncthreads();
    }
    if (k == 0) { g_n = red[0]; out[O_LOSS] = red2[0] / 8388608.0f; }
}

__global__ void ema_b_kernel(const float* __restrict__ embed_avg,
                             float* __restrict__ out) {
    int idx = blockIdx.x * 256 + threadIdx.x;
    int k = idx >> 8;
    float nea = embed_avg[idx] * DECAY_F + ONE_M_DECAY * g_es[idx];
    out[O_EAVG + idx] = nea;
    float ncs = out[O_CS + k];
    float n = g_n;
    float csn = (ncs + EPS_F) / (n + KC * EPS_F) * n;
    out[O_EMB + idx] = nea / csn;
}

// ---------------------------------------------------------------------------
extern "C" void kernel_launch(void* const* d_in, const int* in_sizes, int n_in,
                              void* d_out, int out_size)
{
    const float* z            = (const float*)d_in[0];
    const float* embed        = (const float*)d_in[1];
    const float* cluster_size = (const float*)d_in[2];
    const float* embed_avg    = (const float*)d_in[3];
    float* out = (float*)d_out;

    cudaFuncSetAttribute(dist_hmma_kernel,
                         cudaFuncAttributeMaxDynamicSharedMemorySize, SMEM_TOTAL);

    void* p;
    cudaGetSymbolAddress(&p, g_es);
    cudaMemsetAsync(p, 0, KC * DDIM * sizeof(float));        // launch 1
    cudaGetSymbolAddress(&p, g_cs);
    cudaMemsetAsync(p, 0, KC * sizeof(float));               // launch 2

    pre_kernel<<<1, 32>>>();                                 // launch 3
    split_e_enorm_kernel<<<KC, 256>>>(embed);                // launch 4
    split_x_kernel<<<NTOK / 32, 256>>>(z);                   // launch 5
    dist_hmma_kernel<<<NTOK / 128, 128, SMEM_TOTAL>>>(out);  // launch 6 <- ncu
    gather_kernel<<<NTOK / 32, 256>>>(z, embed, out);
    ema_a_kernel<<<1, KC>>>(cluster_size, out);
    ema_b_kernel<<<KC * DDIM / 256, 256>>>(embed_avg, out);
}

// round 11
// speedup vs baseline: 1.4625x; 1.1928x over previous
#include <cuda_runtime.h>
#include <cuda_bf16.h>
#include <cstdint>

#define NTOK 32768
#define DDIM 256
#define KC   1024
#define HW   1024
#define DECAY_F 0.99f
#define ONE_M_DECAY 0.01f
#define EPS_F 1e-5f
#define CM   16
#define SLACK 0.0625f

// output offsets (concatenated float32 outputs in reference return order)
#define O_ZQ   0
#define O_IDX  8388608
#define O_LOSS 8421376
#define O_EMB  8421377
#define O_CS   8683521
#define O_EAVG 8684545

__device__ float g_es[KC * DDIM];
__device__ float g_cs[KC];
__device__ int   g_idx[NTOK];
__device__ float g_enorm[KC];
__device__ float g_p[KC];          // ||e_k||
__device__ float g_q[KC];          // ||e_k - e_k_hi||
__device__ float g_ta[NTOK];       // 2.004*||x - x_hi||
__device__ float g_tb[NTOK];       // 2.004*||x_hi||
__device__ float g_U[NTOK];        // per-token upper bound on min dist-core
__device__ int   g_ccnt[NTOK];
__device__ int   g_cand[NTOK * CM];
__device__ float g_partial[1024];
__device__ float g_n;
__device__ float g_xf[NTOK * DDIM];   // fp32 flat tokens x dims

// A hi-split in mma-FRAGMENT-MAJOR layout: u32 idx = tblk16*2048 + ks*128 + lane*4 + frag
__device__ __align__(16) uint32_t g_ax0f[NTOK * 128];
// B hi-split row-major (code-major, 512B rows)
__device__ __align__(16) __nv_bfloat16 g_be0[KC * DDIM];

__device__ __forceinline__ uint32_t smem_u32(const void* p) {
    uint32_t a;
    asm("{ .reg .u64 t; cvta.to.shared.u64 t, %1; cvt.u32.u64 %0, t; }"
        : "=r"(a) : "l"(p));
    return a;
}

__device__ __forceinline__ void mma16816(float* c, const uint32_t* a,
                                         uint32_t b0, uint32_t b1) {
    asm volatile(
        "mma.sync.aligned.m16n8k16.row.col.f32.bf16.bf16.f32 "
        "{%0,%1,%2,%3}, {%4,%5,%6,%7}, {%8,%9}, {%0,%1,%2,%3};"
        : "+f"(c[0]), "+f"(c[1]), "+f"(c[2]), "+f"(c[3])
        : "r"(a[0]), "r"(a[1]), "r"(a[2]), "r"(a[3]), "r"(b0), "r"(b1));
}

#define LDSM_X4(r0, r1, r2, r3, addr) \
    asm volatile("ldmatrix.sync.aligned.m8n8.x4.shared.b16 {%0,%1,%2,%3}, [%4];" \
        : "=r"(r0), "=r"(r1), "=r"(r2), "=r"(r3) : "r"(addr))

#define CP_ASYNC16(dst, src) \
    asm volatile("cp.async.cg.shared.global [%0], [%1], 16;" \
                 :: "r"(dst), "l"(src) : "memory")
#define CP_COMMIT() asm volatile("cp.async.commit_group;" ::: "memory")

// ---------------------------------------------------------------------------
// e hi-split + ||e||^2, ||e||, ||delta_e||
// ---------------------------------------------------------------------------
__global__ __launch_bounds__(256) void split_e_kernel(const float* __restrict__ embed) {
    __shared__ float w1[8], w2[8];
    int c = blockIdx.x, tid = threadIdx.x;
    int i = c * DDIM + tid;
    float v = embed[i];
    __nv_bfloat16 h = __float2bfloat16_rn(v);
    g_be0[i] = h;
    float r = v - __bfloat162float(h);
    float s1 = v * v, s2 = r * r;
#pragma unroll
    for (int off = 16; off; off >>= 1) {
        s1 += __shfl_xor_sync(0xffffffffu, s1, off);
        s2 += __shfl_xor_sync(0xffffffffu, s2, off);
    }
    if ((tid & 31) == 0) { w1[tid >> 5] = s1; w2[tid >> 5] = s2; }
    __syncthreads();
    if (tid == 0) {
        float a = 0.f, b = 0.f;
#pragma unroll
        for (int w = 0; w < 8; w++) { a += w1[w]; b += w2[w]; }
        g_enorm[c] = a;
        g_p[c] = sqrtf(a);
        g_q[c] = sqrtf(b);
    }
}

// token-transpose + hi split (fragment-major) + fp32 flat copy + token norms
__global__ __launch_bounds__(256) void split_x_kernel(const float* __restrict__ z) {
    __shared__ float s[32][257];
    __shared__ float pdx[8][32], pxh[8][32];
    int tid = threadIdx.x;
    int t0 = blockIdx.x * 32;
    int bimg = t0 >> 10, hw0 = t0 & 1023;
    int d0 = tid >> 5, ti = tid & 31;
#pragma unroll
    for (int mrow = 0; mrow < 32; mrow++) {
        int d = mrow * 8 + d0;
        s[ti][d] = z[((size_t)bimg * DDIM + d) * HW + hw0 + ti];
    }
    __syncthreads();
    // fp32 flat copy (coalesced)
#pragma unroll
    for (int l = 0; l < 32; l++)
        g_xf[(size_t)(t0 + l) * DDIM + tid] = s[l][tid];
    // per-token norms: warp w sums dims [w*32, w*32+32) for token=lane
    {
        int w = tid >> 5, l = tid & 31;
        float sdx = 0.f, sxh = 0.f;
#pragma unroll
        for (int j = 0; j < 32; j++) {
            int d = w * 32 + j;
            float v = s[l][d];
            float hf = __bfloat162float(__float2bfloat16_rn(v));
            float r = v - hf;
            sdx += r * r;
            sxh += hf * hf;
        }
        pdx[w][l] = sdx; pxh[w][l] = sxh;
    }
    __syncthreads();
    if (tid < 32) {
        float a = 0.f, b = 0.f;
#pragma unroll
        for (int w = 0; w < 8; w++) { a += pdx[w][tid]; b += pxh[w][tid]; }
        g_ta[t0 + tid] = 2.004f * sqrtf(a);
        g_tb[t0 + tid] = 2.004f * sqrtf(b);
    }
    // fragment-major hi pack
    size_t obase = (size_t)(t0 >> 4) * 2048;
#pragma unroll
    for (int i = 0; i < 16; i++) {
        int j = i * 256 + tid;
        int tbl = j >> 11, r = j & 2047;
        int ks = r >> 7, L = (r >> 2) & 31, f = r & 3;
        int g = L >> 2, q = L & 3, half = f & 1, kh = f >> 1;
        int tl = tbl * 16 + half * 8 + g;
        int d = ks * 16 + kh * 8 + q * 2;
        __nv_bfloat16 h0 = __float2bfloat16_rn(s[tl][d]);
        __nv_bfloat16 h1 = __float2bfloat16_rn(s[tl][d + 1]);
        g_ax0f[obase + j] = ((uint32_t)__bfloat16_as_ushort(h1) << 16) | __bfloat16_as_ushort(h0);
    }
}

// ---------------------------------------------------------------------------
// hh-only GEMM passes. Grid 256 x 128 thr, 2 CTAs/SM.
// CTA = 128 tokens (4 warps x m32) x 1024 codes in 16 chunks of 64.
// smem: en 4KB | p 4KB | q 4KB | B 32KB
// PASS==0: track per-token U = min(chat+beta).  PASS==1: collect candidates.
// ---------------------------------------------------------------------------
#define P1_B   12288
#define P1_SMEM (12288 + 32768)

template <int PASS>
__device__ __forceinline__ void dist_pass(float* out)
{
    extern __shared__ __align__(1024) char smem[];
    float* s_en = (float*)smem;
    float* s_p  = (float*)(smem + 4096);
    float* s_q  = (float*)(smem + 8192);
    uint32_t sb = smem_u32(smem);
    int tid = threadIdx.x, wid = tid >> 5, lane = tid & 31;
    int t0 = blockIdx.x * 128;
    int group = lane >> 2, tq = lane & 3;
    int bn = (lane & 7) + ((lane >> 4) << 3);
    int bkh = (lane >> 3) & 1;

#pragma unroll
    for (int i = 0; i < 8; i++) {
        int idx = i * 128 + tid;
        s_en[idx] = g_enorm[idx];
        s_p[idx] = g_p[idx];
        s_q[idx] = g_q[idx];
    }

    int trow[4];
    float a4[4], b4[4], u4[4], minU[4];
#pragma unroll
    for (int mt = 0; mt < 2; mt++)
#pragma unroll
        for (int h = 0; h < 2; h++) {
            int bi = mt * 2 + h;
            trow[bi] = t0 + wid * 32 + mt * 16 + h * 8 + group;
            a4[bi] = g_ta[trow[bi]];
            b4[bi] = g_tb[trow[bi]];
            minU[bi] = 3.4e38f;
            if (PASS == 1) u4[bi] = g_U[trow[bi]];
        }

    size_t abase[2];
#pragma unroll
    for (int mt = 0; mt < 2; mt++)
        abase[mt] = (size_t)(blockIdx.x * 8 + wid * 2 + mt) * 2048 + lane * 4;

    // stage chunk 0: 64 codes x 512B = 32KB
#pragma unroll
    for (int it = 0; it < 16; it++) {
        int id = it * 128 + tid;
        int n = id >> 5, col = id & 31;
        uint32_t dst = sb + P1_B + n * 512 + ((col ^ (n & 7)) << 4);
        CP_ASYNC16(dst, (const char*)g_be0 + (size_t)n * 512 + col * 16);
    }
    CP_COMMIT();

#pragma unroll 1
    for (int nc = 0; nc < 16; nc++) {
        asm volatile("cp.async.wait_group 0;" ::: "memory");
        __syncthreads();

        float acc[4][2][8];
#pragma unroll
        for (int nt = 0; nt < 4; nt++)
#pragma unroll
            for (int mt = 0; mt < 2; mt++)
#pragma unroll
                for (int j = 0; j < 8; j++) acc[nt][mt][j] = 0.f;

        uint4 acur[2], anxt[2];
#pragma unroll
        for (int mt = 0; mt < 2; mt++)
            acur[mt] = *(const uint4*)(g_ax0f + abase[mt]);

#pragma unroll 1
        for (int ks = 0; ks < 16; ks++) {
            if (ks < 15) {
#pragma unroll
                for (int mt = 0; mt < 2; mt++)
                    anxt[mt] = *(const uint4*)(g_ax0f + abase[mt] + (ks + 1) * 128);
            }
#pragma unroll
            for (int nt = 0; nt < 4; nt++) {
                int nl = nt * 16 + bn;
                uint32_t baddr = sb + P1_B + nl * 512 + (((ks * 2 + bkh) ^ (nl & 7)) << 4);
                uint32_t b0, b1, b2, b3;
                LDSM_X4(b0, b1, b2, b3, baddr);
#pragma unroll
                for (int mt = 0; mt < 2; mt++) {
                    mma16816(acc[nt][mt], (const uint32_t*)&acur[mt], b0, b1);
                    mma16816(acc[nt][mt] + 4, (const uint32_t*)&acur[mt], b2, b3);
                }
            }
            acur[0] = anxt[0]; acur[1] = anxt[1];
        }

        __syncthreads();
        if (nc < 15) {
            int n0n = (nc + 1) * 64;
#pragma unroll
            for (int it = 0; it < 16; it++) {
                int id = it * 128 + tid;
                int n = id >> 5, col = id & 31;
                uint32_t dst = sb + P1_B + n * 512 + ((col ^ (n & 7)) << 4);
                CP_ASYNC16(dst, (const char*)g_be0 + (size_t)(n0n + n) * 512 + col * 16);
            }
            CP_COMMIT();
        }

        // fold
        int n0 = nc * 64;
#pragma unroll
        for (int nt = 0; nt < 4; nt++)
#pragma unroll
            for (int mt = 0; mt < 2; mt++)
#pragma unroll
                for (int nh = 0; nh < 2; nh++) {
                    int cb = n0 + nt * 16 + nh * 8 + tq * 2;
                    float2 en = *(const float2*)&s_en[cb];
                    float2 pp = *(const float2*)&s_p[cb];
                    float2 qq = *(const float2*)&s_q[cb];
                    const float* c = &acc[nt][mt][nh * 4];
                    int bi0 = mt * 2, bi1 = mt * 2 + 1;
                    float ch0 = en.x - 2.f * c[0];
                    float bd0 = a4[bi0] * pp.x + b4[bi0] * qq.x + SLACK;
                    float ch1 = en.y - 2.f * c[1];
                    float bd1 = a4[bi0] * pp.y + b4[bi0] * qq.y + SLACK;
                    float ch2 = en.x - 2.f * c[2];
                    float bd2 = a4[bi1] * pp.x + b4[bi1] * qq.x + SLACK;
                    float ch3 = en.y - 2.f * c[3];
                    float bd3 = a4[bi1] * pp.y + b4[bi1] * qq.y + SLACK;
                    if (PASS == 0) {
                        minU[bi0] = fminf(minU[bi0], fminf(ch0 + bd0, ch1 + bd1));
                        minU[bi1] = fminf(minU[bi1], fminf(ch2 + bd2, ch3 + bd3));
                    } else {
                        if (ch0 - bd0 <= u4[bi0]) {
                            int pos = atomicAdd(&g_ccnt[trow[bi0]], 1);
                            if (pos < CM) g_cand[trow[bi0] * CM + pos] = cb;
                        }
                        if (ch1 - bd1 <= u4[bi0]) {
                            int pos = atomicAdd(&g_ccnt[trow[bi0]], 1);
                            if (pos < CM) g_cand[trow[bi0] * CM + pos] = cb + 1;
                        }
                        if (ch2 - bd2 <= u4[bi1]) {
                            int pos = atomicAdd(&g_ccnt[trow[bi1]], 1);
                            if (pos < CM) g_cand[trow[bi1] * CM + pos] = cb;
                        }
                        if (ch3 - bd3 <= u4[bi1]) {
                            int pos = atomicAdd(&g_ccnt[trow[bi1]], 1);
                            if (pos < CM) g_cand[trow[bi1] * CM + pos] = cb + 1;
                        }
                    }
                }
    }

    if (PASS == 0) {
        // quad reduce min, write U and clear counters
#pragma unroll
        for (int off = 1; off <= 2; off <<= 1)
#pragma unroll
            for (int i = 0; i < 4; i++)
                minU[i] = fminf(minU[i], __shfl_xor_sync(0xffffffffu, minU[i], off));
        if ((lane & 3) == 0) {
#pragma unroll
            for (int i = 0; i < 4; i++) {
                g_U[trow[i]] = minU[i];
                g_ccnt[trow[i]] = 0;
            }
        }
    }
}

__global__ __launch_bounds__(128, 2) void distA_kernel(float* __restrict__ out) {
    dist_pass<0>(out);
}
__global__ __launch_bounds__(128, 2) void distB_kernel(float* __restrict__ out) {
    dist_pass<1>(out);
}

// ---------------------------------------------------------------------------
// Resolve: exact fp32 distance over candidates; warp per token.
// ---------------------------------------------------------------------------
__global__ __launch_bounds__(256) void resolve_kernel(
    const float* __restrict__ embed, float* __restrict__ out)
{
    int tid = threadIdx.x, wid = tid >> 5, lane = tid & 31;
    int t = blockIdx.x * 8 + wid;
    const float* xr = g_xf + (size_t)t * DDIM + lane * 8;
    float4 x0 = *(const float4*)xr;
    float4 x1 = *(const float4*)(xr + 4);
    int cnt = g_ccnt[t];
    float best = 3.4e38f;
    int bk = 0;
    bool fallback = (cnt > CM) || (cnt == 0);
    int niter = fallback ? KC : cnt;
    for (int i = 0; i < niter; i++) {
        int k = fallback ? i : g_cand[t * CM + i];
        const float* er = embed + (size_t)k * DDIM + lane * 8;
        float4 e0 = *(const float4*)er;
        float4 e1 = *(const float4*)(er + 4);
        float s = x0.x * e0.x + x0.y * e0.y + x0.z * e0.z + x0.w * e0.w
                + x1.x * e1.x + x1.y * e1.y + x1.z * e1.z + x1.w * e1.w;
#pragma unroll
        for (int off = 16; off; off >>= 1) s += __shfl_xor_sync(0xffffffffu, s, off);
        float c = g_enorm[k] - 2.f * s;
        if (c < best || (c == best && k < bk)) { best = c; bk = k; }
    }
    if (lane == 0) {
        g_idx[t] = bk;
        out[O_IDX + t] = (float)bk;
        atomicAdd(&g_cs[bk], 1.0f);
    }
}

// ---------------------------------------------------------------------------
// Gather z_q, vq_loss partials, es segment-sum (v4 atomics, shuffle reduce)
// ---------------------------------------------------------------------------
__global__ __launch_bounds__(256) void gather_kernel(
    const float* __restrict__ z, const float* __restrict__ embed,
    float* __restrict__ out)
{
    __shared__ float s2[DDIM][33];
    __shared__ int   kidx[32];
    __shared__ float wred[8];
    int tid = threadIdx.x;
    int t0 = blockIdx.x * 32;
    int bimg = t0 >> 10, hw0 = t0 & 1023;

    if (tid < 32) kidx[tid] = g_idx[t0 + tid];
    __syncthreads();
#pragma unroll
    for (int l = 0; l < 32; l++)
        s2[tid][l] = embed[(size_t)kidx[l] * DDIM + tid];
    __syncthreads();

    int ti = tid & 31, dq = (tid >> 5) * 4;
    int myk = kidx[ti];
    float* esrow = &g_es[(size_t)myk * DDIM];
    float lsum = 0.f;
    const float* zb = z + (size_t)bimg * DDIM * HW + hw0 + ti;
    float* ob = out + O_ZQ + (size_t)bimg * DDIM * HW + hw0 + ti;
#pragma unroll
    for (int m = 0; m < 8; m++) {
        int d = m * 32 + dq;
        float e0 = s2[d][ti], e1 = s2[d + 1][ti], e2 = s2[d + 2][ti], e3 = s2[d + 3][ti];
        size_t zo = (size_t)d * HW;
        float z0 = zb[zo], z1 = zb[zo + HW], z2 = zb[zo + 2 * HW], z3 = zb[zo + 3 * HW];
        ob[zo] = e0; ob[zo + HW] = e1; ob[zo + 2 * HW] = e2; ob[zo + 3 * HW] = e3;
        float f0 = z0 - e0, f1 = z1 - e1, f2 = z2 - e2, f3 = z3 - e3;
        lsum += f0 * f0 + f1 * f1 + f2 * f2 + f3 * f3;
        asm volatile("red.global.add.v4.f32 [%0], {%1, %2, %3, %4};"
                     :: "l"(esrow + d), "f"(z0), "f"(z1), "f"(z2), "f"(z3) : "memory");
    }
#pragma unroll
    for (int off = 16; off; off >>= 1) lsum += __shfl_xor_sync(0xffffffffu, lsum, off);
    if ((tid & 31) == 0) wred[tid >> 5] = lsum;
    __syncthreads();
    if (tid == 0) {
        float s = 0.f;
#pragma unroll
        for (int w = 0; w < 8; w++) s += wred[w];
        g_partial[blockIdx.x] = s;
    }
}

// loss finalize + EMA cluster-size + n (single block)
__global__ void ema_a_kernel(const float* __restrict__ cluster_size,
                             float* __restrict__ out) {
    __shared__ float red[KC];
    __shared__ float red2[KC];
    int k = threadIdx.x;
    float ncs = cluster_size[k] * DECAY_F + ONE_M_DECAY * g_cs[k];
    out[O_CS + k] = ncs;
    red[k] = ncs;
    red2[k] = g_partial[k];
    __syncthreads();
    for (int off = 512; off; off >>= 1) {
        if (k < off) { red[k] += red[k + off]; red2[k] += red2[k + off]; }
        __syncthreads();
    }
    if (k == 0) { g_n = red[0]; out[O_LOSS] = red2[0] / 8388608.0f; }
}

__global__ void ema_b_kernel(const float* __restrict__ embed_avg,
                             float* __restrict__ out) {
    int idx = blockIdx.x * 256 + threadIdx.x;
    int k = idx >> 8;
    float nea = embed_avg[idx] * DECAY_F + ONE_M_DECAY * g_es[idx];
    out[O_EAVG + idx] = nea;
    float ncs = out[O_CS + k];
    float n = g_n;
    float csn = (ncs + EPS_F) / (n + KC * EPS_F) * n;
    out[O_EMB + idx] = nea / csn;
}

// ---------------------------------------------------------------------------
extern "C" void kernel_launch(void* const* d_in, const int* in_sizes, int n_in,
                              void* d_out, int out_size)
{
    const float* z            = (const float*)d_in[0];
    const float* embed        = (const float*)d_in[1];
    const float* cluster_size = (const float*)d_in[2];
    const float* embed_avg    = (const float*)d_in[3];
    float* out = (float*)d_out;

    cudaFuncSetAttribute(distA_kernel,
                         cudaFuncAttributeMaxDynamicSharedMemorySize, P1_SMEM);
    cudaFuncSetAttribute(distB_kernel,
                         cudaFuncAttributeMaxDynamicSharedMemorySize, P1_SMEM);

    void* p;
    cudaGetSymbolAddress(&p, g_es);
    cudaMemsetAsync(p, 0, KC * DDIM * sizeof(float));          // launch 1
    cudaGetSymbolAddress(&p, g_cs);
    cudaMemsetAsync(p, 0, KC * sizeof(float));                 // launch 2

    split_e_kernel<<<KC, 256>>>(embed);                        // launch 3
    split_x_kernel<<<NTOK / 32, 256>>>(z);                     // launch 4
    distA_kernel<<<NTOK / 128, 128, P1_SMEM>>>(out);           // launch 5
    distB_kernel<<<NTOK / 128, 128, P1_SMEM>>>(out);           // launch 6 <- ncu
    resolve_kernel<<<NTOK / 8, 256>>>(embed, out);             // launch 7
    gather_kernel<<<NTOK / 32, 256>>>(z, embed, out);          // launch 8
    ema_a_kernel<<<1, KC>>>(cluster_size, out);                // launch 9
    ema_b_kernel<<<KC * DDIM / 256, 256>>>(embed_avg, out);    // launch 10
}

// round 12
// speedup vs baseline: 1.8607x; 1.2723x over previous
#include <cuda_runtime.h>
#include <cuda_bf16.h>
#include <cuda_fp16.h>
#include <cstdint>

#define NTOK 32768
#define DDIM 256
#define KC   1024
#define HW   1024
#define DECAY_F 0.99f
#define ONE_M_DECAY 0.01f
#define EPS_F 1e-5f
#define CM   16
#define SLACK 0.0625f
#define FP16_MARGIN 1.0f

// output offsets (concatenated float32 outputs in reference return order)
#define O_ZQ   0
#define O_IDX  8388608
#define O_LOSS 8421376
#define O_EMB  8421377
#define O_CS   8683521
#define O_EAVG 8684545

__device__ float g_es[KC * DDIM];
__device__ float g_cs[KC];
__device__ int   g_idx[NTOK];
__device__ float g_enorm[KC];
__device__ float g_p[KC];          // ||e_k||
__device__ float g_q[KC];          // ||e_k - e_k_hi||
__device__ float g_ta[NTOK];       // 2.004*||x - x_hi||
__device__ float g_tb[NTOK];       // 2.004*||x_hi||
__device__ int   g_ccnt[NTOK];
__device__ int   g_cand[NTOK * CM];
__device__ float g_partial[1024];
__device__ float g_n;
__device__ float g_xf[NTOK * DDIM];          // fp32 flat tokens x dims
__device__ __align__(16) __half g_chat[NTOK * KC];   // hh-GEMM estimates

// A hi-split, mma-FRAGMENT-MAJOR: u32 idx = tblk16*2048 + ks*128 + lane*4 + frag
__device__ __align__(16) uint32_t g_ax0f[NTOK * 128];
// B hi-split row-major (code-major, 512B rows)
__device__ __align__(16) __nv_bfloat16 g_be0[KC * DDIM];

__device__ __forceinline__ uint32_t smem_u32(const void* p) {
    uint32_t a;
    asm("{ .reg .u64 t; cvta.to.shared.u64 t, %1; cvt.u32.u64 %0, t; }"
        : "=r"(a) : "l"(p));
    return a;
}

__device__ __forceinline__ void mma16816(float* c, const uint32_t* a,
                                         uint32_t b0, uint32_t b1) {
    asm volatile(
        "mma.sync.aligned.m16n8k16.row.col.f32.bf16.bf16.f32 "
        "{%0,%1,%2,%3}, {%4,%5,%6,%7}, {%8,%9}, {%0,%1,%2,%3};"
        : "+f"(c[0]), "+f"(c[1]), "+f"(c[2]), "+f"(c[3])
        : "r"(a[0]), "r"(a[1]), "r"(a[2]), "r"(a[3]), "r"(b0), "r"(b1));
}

#define LDSM_X4(r0, r1, r2, r3, addr) \
    asm volatile("ldmatrix.sync.aligned.m8n8.x4.shared.b16 {%0,%1,%2,%3}, [%4];" \
        : "=r"(r0), "=r"(r1), "=r"(r2), "=r"(r3) : "r"(addr))

#define CP_ASYNC16(dst, src) \
    asm volatile("cp.async.cg.shared.global [%0], [%1], 16;" \
                 :: "r"(dst), "l"(src) : "memory")
#define CP_COMMIT() asm volatile("cp.async.commit_group;" ::: "memory")

__global__ void pre_kernel() { if (threadIdx.x == 0) g_n = 0.f; }

// ---------------------------------------------------------------------------
// e hi-split + ||e||^2, ||e||, ||delta_e||
// ---------------------------------------------------------------------------
__global__ __launch_bounds__(256) void split_e_kernel(const float* __restrict__ embed) {
    __shared__ float w1[8], w2[8];
    int c = blockIdx.x, tid = threadIdx.x;
    int i = c * DDIM + tid;
    float v = embed[i];
    __nv_bfloat16 h = __float2bfloat16_rn(v);
    g_be0[i] = h;
    float r = v - __bfloat162float(h);
    float s1 = v * v, s2 = r * r;
#pragma unroll
    for (int off = 16; off; off >>= 1) {
        s1 += __shfl_xor_sync(0xffffffffu, s1, off);
        s2 += __shfl_xor_sync(0xffffffffu, s2, off);
    }
    if ((tid & 31) == 0) { w1[tid >> 5] = s1; w2[tid >> 5] = s2; }
    __syncthreads();
    if (tid == 0) {
        float a = 0.f, b = 0.f;
#pragma unroll
        for (int w = 0; w < 8; w++) { a += w1[w]; b += w2[w]; }
        g_enorm[c] = a;
        g_p[c] = sqrtf(a);
        g_q[c] = sqrtf(b);
    }
}

// token-transpose + hi split (fragment-major) + fp32 flat copy + token norms
__global__ __launch_bounds__(256) void split_x_kernel(const float* __restrict__ z) {
    __shared__ float s[32][257];
    __shared__ float pdx[8][32], pxh[8][32];
    int tid = threadIdx.x;
    int t0 = blockIdx.x * 32;
    int bimg = t0 >> 10, hw0 = t0 & 1023;
    int d0 = tid >> 5, ti = tid & 31;
#pragma unroll
    for (int mrow = 0; mrow < 32; mrow++) {
        int d = mrow * 8 + d0;
        s[ti][d] = z[((size_t)bimg * DDIM + d) * HW + hw0 + ti];
    }
    __syncthreads();
#pragma unroll
    for (int l = 0; l < 32; l++)
        g_xf[(size_t)(t0 + l) * DDIM + tid] = s[l][tid];
    {
        int w = tid >> 5, l = tid & 31;
        float sdx = 0.f, sxh = 0.f;
#pragma unroll
        for (int j = 0; j < 32; j++) {
            int d = w * 32 + j;
            float v = s[l][d];
            float hf = __bfloat162float(__float2bfloat16_rn(v));
            float r = v - hf;
            sdx += r * r;
            sxh += hf * hf;
        }
        pdx[w][l] = sdx; pxh[w][l] = sxh;
    }
    __syncthreads();
    if (tid < 32) {
        float a = 0.f, b = 0.f;
#pragma unroll
        for (int w = 0; w < 8; w++) { a += pdx[w][tid]; b += pxh[w][tid]; }
        g_ta[t0 + tid] = 2.004f * sqrtf(a);
        g_tb[t0 + tid] = 2.004f * sqrtf(b);
    }
    size_t obase = (size_t)(t0 >> 4) * 2048;
#pragma unroll
    for (int i = 0; i < 16; i++) {
        int j = i * 256 + tid;
        int tbl = j >> 11, r = j & 2047;
        int ks = r >> 7, L = (r >> 2) & 31, f = r & 3;
        int g = L >> 2, q = L & 3, half = f & 1, kh = f >> 1;
        int tl = tbl * 16 + half * 8 + g;
        int d = ks * 16 + kh * 8 + q * 2;
        __nv_bfloat16 h0 = __float2bfloat16_rn(s[tl][d]);
        __nv_bfloat16 h1 = __float2bfloat16_rn(s[tl][d + 1]);
        g_ax0f[obase + j] = ((uint32_t)__bfloat16_as_ushort(h1) << 16) | __bfloat16_as_ushort(h0);
    }
}

// ---------------------------------------------------------------------------
// distA: pure hh GEMM -> g_chat fp16. Grid 256 x 128 thr, 2 CTAs/SM.
// CTA = 128 tokens (4 warps x m32) x 1024 codes in 16 chunks of 64.
// B double-buffered (2 x 32KB, cp.async); A reg double-buffer from L2.
// No fold, no bound math here.
// ---------------------------------------------------------------------------
#define DB_BYTES 32768
#define PA_SMEM (2 * DB_BYTES)

__global__ __launch_bounds__(128, 2) void distA_kernel()
{
    extern __shared__ __align__(1024) char smem[];
    uint32_t sb = smem_u32(smem);
    int tid = threadIdx.x, wid = tid >> 5, lane = tid & 31;
    int t0 = blockIdx.x * 128;
    int group = lane >> 2, tq = lane & 3;
    int bn = (lane & 7) + ((lane >> 4) << 3);
    int bkh = (lane >> 3) & 1;

    size_t abase[2];
#pragma unroll
    for (int mt = 0; mt < 2; mt++)
        abase[mt] = (size_t)(blockIdx.x * 8 + wid * 2 + mt) * 2048 + lane * 4;

    // stage chunk 0 into buf0: 64 codes x 512B = 32KB
#pragma unroll
    for (int it = 0; it < 16; it++) {
        int id = it * 128 + tid;
        int n = id >> 5, col = id & 31;
        uint32_t dst = sb + n * 512 + ((col ^ (n & 7)) << 4);
        CP_ASYNC16(dst, (const char*)g_be0 + (size_t)n * 512 + col * 16);
    }
    CP_COMMIT();

#pragma unroll 1
    for (int nc = 0; nc < 16; nc++) {
        if (nc < 15) {
            int n0n = (nc + 1) * 64;
            uint32_t bufn = sb + ((nc + 1) & 1) * DB_BYTES;
#pragma unroll
            for (int it = 0; it < 16; it++) {
                int id = it * 128 + tid;
                int n = id >> 5, col = id & 31;
                uint32_t dst = bufn + n * 512 + ((col ^ (n & 7)) << 4);
                CP_ASYNC16(dst, (const char*)g_be0 + (size_t)(n0n + n) * 512 + col * 16);
            }
            CP_COMMIT();
            asm volatile("cp.async.wait_group 1;" ::: "memory");
        } else {
            asm volatile("cp.async.wait_group 0;" ::: "memory");
        }
        __syncthreads();

        uint32_t bbase = sb + (nc & 1) * DB_BYTES;
        float acc[4][2][8];
#pragma unroll
        for (int nt = 0; nt < 4; nt++)
#pragma unroll
            for (int mt = 0; mt < 2; mt++)
#pragma unroll
                for (int j = 0; j < 8; j++) acc[nt][mt][j] = 0.f;

        uint4 acur[2], anxt[2];
#pragma unroll
        for (int mt = 0; mt < 2; mt++)
            acur[mt] = *(const uint4*)(g_ax0f + abase[mt]);

#pragma unroll 1
        for (int ks = 0; ks < 16; ks++) {
            if (ks < 15) {
#pragma unroll
                for (int mt = 0; mt < 2; mt++)
                    anxt[mt] = *(const uint4*)(g_ax0f + abase[mt] + (ks + 1) * 128);
            }
#pragma unroll
            for (int nt = 0; nt < 4; nt++) {
                int nl = nt * 16 + bn;
                uint32_t baddr = bbase + nl * 512 + (((ks * 2 + bkh) ^ (nl & 7)) << 4);
                uint32_t b0, b1, b2, b3;
                LDSM_X4(b0, b1, b2, b3, baddr);
#pragma unroll
                for (int mt = 0; mt < 2; mt++) {
                    mma16816(acc[nt][mt], (const uint32_t*)&acur[mt], b0, b1);
                    mma16816(acc[nt][mt] + 4, (const uint32_t*)&acur[mt], b2, b3);
                }
            }
            acur[0] = anxt[0]; acur[1] = anxt[1];
        }

        // store chat estimates (fp16): chat = acc (codes), collect adds enorm
        int n0 = nc * 64;
#pragma unroll
        for (int nt = 0; nt < 4; nt++)
#pragma unroll
            for (int mt = 0; mt < 2; mt++) {
                int row0 = t0 + wid * 32 + mt * 16 + group;
#pragma unroll
                for (int nh = 0; nh < 2; nh++) {
                    int cb = n0 + nt * 16 + nh * 8 + tq * 2;
                    const float* c = &acc[nt][mt][nh * 4];
                    *(__half2*)(g_chat + (size_t)row0 * KC + cb) =
                        __floats2half2_rn(c[0], c[1]);
                    *(__half2*)(g_chat + (size_t)(row0 + 8) * KC + cb) =
                        __floats2half2_rn(c[2], c[3]);
                }
            }
        __syncthreads();   // all warps done with this buffer before restage
    }
}

// ---------------------------------------------------------------------------
// collect: warp per token. Reads fp16 chat row (2KB coalesced), computes
// U = min(en - 2*chat + bd) and candidates (en - 2*chat) - bd <= U + margin.
// Ballot-based list emission, no atomics.
// ---------------------------------------------------------------------------
__global__ __launch_bounds__(256) void collect_kernel()
{
    __shared__ float sp[KC], sq[KC], sen[KC];
    int tid = threadIdx.x, wid = tid >> 5, lane = tid & 31;
    for (int i = tid; i < KC; i += 256) {
        sp[i] = g_p[i]; sq[i] = g_q[i]; sen[i] = g_enorm[i];
    }
    __syncthreads();

    int t = blockIdx.x * 8 + wid;
    float a = g_ta[t], b = g_tb[t];
    const __half2* ch = (const __half2*)(g_chat + (size_t)t * KC);

    __half2 v[16];
    float U = 3.4e38f;
#pragma unroll
    for (int j = 0; j < 16; j++) {
        v[j] = ch[j * 32 + lane];
        int k0 = (j * 32 + lane) * 2;
        float2 c2 = __half22float2(v[j]);
        float ch0 = sen[k0] - 2.f * c2.x;
        float ch1 = sen[k0 + 1] - 2.f * c2.y;
        float bd0 = a * sp[k0] + b * sq[k0] + SLACK;
        float bd1 = a * sp[k0 + 1] + b * sq[k0 + 1] + SLACK;
        U = fminf(U, fminf(ch0 + bd0, ch1 + bd1));
    }
#pragma unroll
    for (int off = 16; off; off >>= 1)
        U = fminf(U, __shfl_xor_sync(0xffffffffu, U, off));
    float thr = U + FP16_MARGIN;

    int cnt = 0;
    unsigned lmask = (1u << lane) - 1u;
#pragma unroll
    for (int j = 0; j < 16; j++) {
        int k0 = (j * 32 + lane) * 2;
        float2 c2 = __half22float2(v[j]);
        float ch0 = sen[k0] - 2.f * c2.x;
        float ch1 = sen[k0 + 1] - 2.f * c2.y;
        float bd0 = a * sp[k0] + b * sq[k0] + SLACK;
        float bd1 = a * sp[k0 + 1] + b * sq[k0 + 1] + SLACK;
        bool p0 = (ch0 - bd0 <= thr);
        bool p1 = (ch1 - bd1 <= thr);
        unsigned m0 = __ballot_sync(0xffffffffu, p0);
        if (p0) {
            int pos = cnt + __popc(m0 & lmask);
            if (pos < CM) g_cand[t * CM + pos] = k0;
        }
        cnt += __popc(m0);
        unsigned m1 = __ballot_sync(0xffffffffu, p1);
        if (p1) {
            int pos = cnt + __popc(m1 & lmask);
            if (pos < CM) g_cand[t * CM + pos] = k0 + 1;
        }
        cnt += __popc(m1);
    }
    if (lane == 0) g_ccnt[t] = cnt;
}

// ---------------------------------------------------------------------------
// Resolve: exact fp32 distance over candidates; warp per token.
// ---------------------------------------------------------------------------
__global__ __launch_bounds__(256) void resolve_kernel(
    const float* __restrict__ embed, float* __restrict__ out)
{
    int tid = threadIdx.x, wid = tid >> 5, lane = tid & 31;
    int t = blockIdx.x * 8 + wid;
    const float* xr = g_xf + (size_t)t * DDIM + lane * 8;
    float4 x0 = *(const float4*)xr;
    float4 x1 = *(const float4*)(xr + 4);
    int cnt = g_ccnt[t];
    float best = 3.4e38f;
    int bk = 0;
    bool fallback = (cnt > CM) || (cnt == 0);
    int niter = fallback ? KC : cnt;
    for (int i = 0; i < niter; i++) {
        int k = fallback ? i : g_cand[t * CM + i];
        const float* er = embed + (size_t)k * DDIM + lane * 8;
        float4 e0 = *(const float4*)er;
        float4 e1 = *(const float4*)(er + 4);
        float s = x0.x * e0.x + x0.y * e0.y + x0.z * e0.z + x0.w * e0.w
                + x1.x * e1.x + x1.y * e1.y + x1.z * e1.z + x1.w * e1.w;
#pragma unroll
        for (int off = 16; off; off >>= 1) s += __shfl_xor_sync(0xffffffffu, s, off);
        float c = g_enorm[k] - 2.f * s;
        if (c < best || (c == best && k < bk)) { best = c; bk = k; }
    }
    if (lane == 0) {
        g_idx[t] = bk;
        out[O_IDX + t] = (float)bk;
        atomicAdd(&g_cs[bk], 1.0f);
    }
}

// ---------------------------------------------------------------------------
// Gather z_q, vq_loss partials, es segment-sum (v4 atomics, shuffle reduce)
// ---------------------------------------------------------------------------
__global__ __launch_bounds__(256) void gather_kernel(
    const float* __restrict__ z, const float* __restrict__ embed,
    float* __restrict__ out)
{
    __shared__ float s2[DDIM][33];
    __shared__ int   kidx[32];
    __shared__ float wred[8];
    int tid = threadIdx.x;
    int t0 = blockIdx.x * 32;
    int bimg = t0 >> 10, hw0 = t0 & 1023;

    if (tid < 32) kidx[tid] = g_idx[t0 + tid];
    __syncthreads();
#pragma unroll
    for (int l = 0; l < 32; l++)
        s2[tid][l] = embed[(size_t)kidx[l] * DDIM + tid];
    __syncthreads();

    int ti = tid & 31, dq = (tid >> 5) * 4;
    int myk = kidx[ti];
    float* esrow = &g_es[(size_t)myk * DDIM];
    float lsum = 0.f;
    const float* zb = z + (size_t)bimg * DDIM * HW + hw0 + ti;
    float* ob = out + O_ZQ + (size_t)bimg * DDIM * HW + hw0 + ti;
#pragma unroll
    for (int m = 0; m < 8; m++) {
        int d = m * 32 + dq;
        float e0 = s2[d][ti], e1 = s2[d + 1][ti], e2 = s2[d + 2][ti], e3 = s2[d + 3][ti];
        size_t zo = (size_t)d * HW;
        float z0 = zb[zo], z1 = zb[zo + HW], z2 = zb[zo + 2 * HW], z3 = zb[zo + 3 * HW];
        ob[zo] = e0; ob[zo + HW] = e1; ob[zo + 2 * HW] = e2; ob[zo + 3 * HW] = e3;
        float f0 = z0 - e0, f1 = z1 - e1, f2 = z2 - e2, f3 = z3 - e3;
        lsum += f0 * f0 + f1 * f1 + f2 * f2 + f3 * f3;
        asm volatile("red.global.add.v4.f32 [%0], {%1, %2, %3, %4};"
                     :: "l"(esrow + d), "f"(z0), "f"(z1), "f"(z2), "f"(z3) : "memory");
    }
#pragma unroll
    for (int off = 16; off; off >>= 1) lsum += __shfl_xor_sync(0xffffffffu, lsum, off);
    if ((tid & 31) == 0) wred[tid >> 5] = lsum;
    __syncthreads();
    if (tid == 0) {
        float s = 0.f;
#pragma unroll
        for (int w = 0; w < 8; w++) s += wred[w];
        g_partial[blockIdx.x] = s;
    }
}

// loss finalize + EMA cluster-size + n (single block)
__global__ void ema_a_kernel(const float* __restrict__ cluster_size,
                             float* __restrict__ out) {
    __shared__ float red[KC];
    __shared__ float red2[KC];
    int k = threadIdx.x;
    float ncs = cluster_size[k] * DECAY_F + ONE_M_DECAY * g_cs[k];
    out[O_CS + k] = ncs;
    red[k] = ncs;
    red2[k] = g_partial[k];
    __syncthreads();
    for (int off = 512; off; off >>= 1) {
        if (k < off) { red[k] += red[k + off]; red2[k] += red2[k + off]; }
        __syncthreads();
    }
    if (k == 0) { g_n = red[0]; out[O_LOSS] = red2[0] / 8388608.0f; }
}

__global__ void ema_b_kernel(const float* __restrict__ embed_avg,
                             float* __restrict__ out) {
    int idx = blockIdx.x * 256 + threadIdx.x;
    int k = idx >> 8;
    float nea = embed_avg[idx] * DECAY_F + ONE_M_DECAY * g_es[idx];
    out[O_EAVG + idx] = nea;
    float ncs = out[O_CS + k];
    float n = g_n;
    float csn = (ncs + EPS_F) / (n + KC * EPS_F) * n;
    out[O_EMB + idx] = nea / csn;
}

// ---------------------------------------------------------------------------
extern "C" void kernel_launch(void* const* d_in, const int* in_sizes, int n_in,
                              void* d_out, int out_size)
{
    const float* z            = (const float*)d_in[0];
    const float* embed        = (const float*)d_in[1];
    const float* cluster_size = (const float*)d_in[2];
    const float* embed_avg    = (const float*)d_in[3];
    float* out = (float*)d_out;

    cudaFuncSetAttribute(distA_kernel,
                         cudaFuncAttributeMaxDynamicSharedMemorySize, PA_SMEM);

    void* p;
    cudaGetSymbolAddress(&p, g_es);
    cudaMemsetAsync(p, 0, KC * DDIM * sizeof(float));          // launch 1
    cudaGetSymbolAddress(&p, g_cs);
    cudaMemsetAsync(p, 0, KC * sizeof(float));                 // launch 2

    split_e_kernel<<<KC, 256>>>(embed);                        // launch 3
    split_x_kernel<<<NTOK / 32, 256>>>(z);                     // launch 4
    pre_kernel<<<1, 32>>>();                                   // launch 5
    distA_kernel<<<NTOK / 128, 128, PA_SMEM>>>();              // launch 6 <- ncu
    collect_kernel<<<NTOK / 8, 256>>>();                       // launch 7
    resolve_kernel<<<NTOK / 8, 256>>>(embed, out);             // launch 8
    gather_kernel<<<NTOK / 32, 256>>>(z, embed, out);          // launch 9
    ema_a_kernel<<<1, KC>>>(cluster_size, out);                // launch 10
    ema_b_kernel<<<KC * DDIM / 256, 256>>>(embed_avg, out);    // launch 11
}

// round 16
// speedup vs baseline: 1.9402x; 1.0427x over previous
#include <cuda_runtime.h>
#include <cuda_bf16.h>
#include <cuda_fp16.h>
#include <cstdint>

#define NTOK 32768
#define DDIM 256
#define KC   1024
#define HW   1024
#define DECAY_F 0.99f
#define ONE_M_DECAY 0.01f
#define EPS_F 1e-5f
#define CM   16
#define SLACK 0.0625f
#define FP16_MARGIN 1.0f

// output offsets (concatenated float32 outputs in reference return order)
#define O_ZQ   0
#define O_IDX  8388608
#define O_LOSS 8421376
#define O_EMB  8421377
#define O_CS   8683521
#define O_EAVG 8684545

__device__ float g_es[KC * DDIM];
__device__ float g_cs[KC];
__device__ int   g_idx[NTOK];
__device__ float g_enorm[KC];
__device__ float g_p[KC];          // ||e_k||
__device__ float g_q[KC];          // ||e_k - e_k_hi||
__device__ float g_ta[NTOK];       // 2.004*||x - x_hi||
__device__ float g_tb[NTOK];       // 2.004*||x_hi||
__device__ int   g_ccnt[NTOK];
__device__ int   g_cand[NTOK * CM];
__device__ float g_partial[1024];
__device__ float g_n;
__device__ __align__(16) __half g_chat[NTOK * KC];   // hh-GEMM estimates

// A hi-split, mma-FRAGMENT-MAJOR: u32 idx = tblk16*2048 + ks*128 + lane*4 + frag
__device__ __align__(16) uint32_t g_ax0f[NTOK * 128];
// B hi-split row-major (code-major, 512B rows)
__device__ __align__(16) __nv_bfloat16 g_be0[KC * DDIM];

__device__ __forceinline__ uint32_t smem_u32(const void* p) {
    uint32_t a;
    asm("{ .reg .u64 t; cvta.to.shared.u64 t, %1; cvt.u32.u64 %0, t; }"
        : "=r"(a) : "l"(p));
    return a;
}

__device__ __forceinline__ void mma16816(float* c, const uint32_t* a,
                                         uint32_t b0, uint32_t b1) {
    asm volatile(
        "mma.sync.aligned.m16n8k16.row.col.f32.bf16.bf16.f32 "
        "{%0,%1,%2,%3}, {%4,%5,%6,%7}, {%8,%9}, {%0,%1,%2,%3};"
        : "+f"(c[0]), "+f"(c[1]), "+f"(c[2]), "+f"(c[3])
        : "r"(a[0]), "r"(a[1]), "r"(a[2]), "r"(a[3]), "r"(b0), "r"(b1));
}

#define LDSM_X4(r0, r1, r2, r3, addr) \
    asm volatile("ldmatrix.sync.aligned.m8n8.x4.shared.b16 {%0,%1,%2,%3}, [%4];" \
        : "=r"(r0), "=r"(r1), "=r"(r2), "=r"(r3) : "r"(addr))

#define CP_ASYNC16(dst, src) \
    asm volatile("cp.async.cg.shared.global [%0], [%1], 16;" \
                 :: "r"(dst), "l"(src) : "memory")
#define CP_COMMIT() asm volatile("cp.async.commit_group;" ::: "memory")

// ---------------------------------------------------------------------------
// e hi-split + ||e||^2, ||e||, ||delta_e||
// ---------------------------------------------------------------------------
__global__ __launch_bounds__(256) void split_e_kernel(const float* __restrict__ embed) {
    __shared__ float w1[8], w2[8];
    int c = blockIdx.x, tid = threadIdx.x;
    int i = c * DDIM + tid;
    float v = embed[i];
    __nv_bfloat16 h = __float2bfloat16_rn(v);
    g_be0[i] = h;
    float r = v - __bfloat162float(h);
    float s1 = v * v, s2 = r * r;
#pragma unroll
    for (int off = 16; off; off >>= 1) {
        s1 += __shfl_xor_sync(0xffffffffu, s1, off);
        s2 += __shfl_xor_sync(0xffffffffu, s2, off);
    }
    if ((tid & 31) == 0) { w1[tid >> 5] = s1; w2[tid >> 5] = s2; }
    __syncthreads();
    if (tid == 0) {
        float a = 0.f, b = 0.f;
#pragma unroll
        for (int w = 0; w < 8; w++) { a += w1[w]; b += w2[w]; }
        g_enorm[c] = a;
        g_p[c] = sqrtf(a);
        g_q[c] = sqrtf(b);
    }
}

// token-transpose + hi split (fragment-major) + token norms (no fp32 copy)
__global__ __launch_bounds__(256) void split_x_kernel(const float* __restrict__ z) {
    __shared__ float s[32][257];
    __shared__ float pdx[8][32], pxh[8][32];
    int tid = threadIdx.x;
    int t0 = blockIdx.x * 32;
    int bimg = t0 >> 10, hw0 = t0 & 1023;
    int d0 = tid >> 5, ti = tid & 31;
#pragma unroll
    for (int mrow = 0; mrow < 32; mrow++) {
        int d = mrow * 8 + d0;
        s[ti][d] = z[((size_t)bimg * DDIM + d) * HW + hw0 + ti];
    }
    __syncthreads();
    {
        int w = tid >> 5, l = tid & 31;
        float sdx = 0.f, sxh = 0.f;
#pragma unroll
        for (int j = 0; j < 32; j++) {
            int d = w * 32 + j;
            float v = s[l][d];
            float hf = __bfloat162float(__float2bfloat16_rn(v));
            float r = v - hf;
            sdx += r * r;
            sxh += hf * hf;
        }
        pdx[w][l] = sdx; pxh[w][l] = sxh;
    }
    __syncthreads();
    if (tid < 32) {
        float a = 0.f, b = 0.f;
#pragma unroll
        for (int w = 0; w < 8; w++) { a += pdx[w][tid]; b += pxh[w][tid]; }
        g_ta[t0 + tid] = 2.004f * sqrtf(a);
        g_tb[t0 + tid] = 2.004f * sqrtf(b);
    }
    size_t obase = (size_t)(t0 >> 4) * 2048;
#pragma unroll
    for (int i = 0; i < 16; i++) {
        int j = i * 256 + tid;
        int tbl = j >> 11, r = j & 2047;
        int ks = r >> 7, L = (r >> 2) & 31, f = r & 3;
        int g = L >> 2, q = L & 3, half = f & 1, kh = f >> 1;
        int tl = tbl * 16 + half * 8 + g;
        int d = ks * 16 + kh * 8 + q * 2;
        __nv_bfloat16 h0 = __float2bfloat16_rn(s[tl][d]);
        __nv_bfloat16 h1 = __float2bfloat16_rn(s[tl][d + 1]);
        g_ax0f[obase + j] = ((uint32_t)__bfloat16_as_ushort(h1) << 16) | __bfloat16_as_ushort(h0);
    }
}

// ---------------------------------------------------------------------------
// distA: pure hh GEMM -> g_chat fp16. Grid 256 x 128 thr, 2 CTAs/SM.
// CTA = 128 tokens (4 warps x m32) x 1024 codes in 16 chunks of 64.
// B double-buffered (2 x 32KB, cp.async); A reg double-buffer from L2.
// ---------------------------------------------------------------------------
#define DB_BYTES 32768
#define PA_SMEM (2 * DB_BYTES)

__global__ __launch_bounds__(128, 2) void distA_kernel()
{
    extern __shared__ __align__(1024) char smem[];
    uint32_t sb = smem_u32(smem);
    int tid = threadIdx.x, wid = tid >> 5, lane = tid & 31;
    int t0 = blockIdx.x * 128;
    int group = lane >> 2, tq = lane & 3;
    int bn = (lane & 7) + ((lane >> 4) << 3);
    int bkh = (lane >> 3) & 1;

    size_t abase[2];
#pragma unroll
    for (int mt = 0; mt < 2; mt++)
        abase[mt] = (size_t)(blockIdx.x * 8 + wid * 2 + mt) * 2048 + lane * 4;

#pragma unroll
    for (int it = 0; it < 16; it++) {
        int id = it * 128 + tid;
        int n = id >> 5, col = id & 31;
        uint32_t dst = sb + n * 512 + ((col ^ (n & 7)) << 4);
        CP_ASYNC16(dst, (const char*)g_be0 + (size_t)n * 512 + col * 16);
    }
    CP_COMMIT();

#pragma unroll 1
    for (int nc = 0; nc < 16; nc++) {
        if (nc < 15) {
            int n0n = (nc + 1) * 64;
            uint32_t bufn = sb + ((nc + 1) & 1) * DB_BYTES;
#pragma unroll
            for (int it = 0; it < 16; it++) {
                int id = it * 128 + tid;
                int n = id >> 5, col = id & 31;
                uint32_t dst = bufn + n * 512 + ((col ^ (n & 7)) << 4);
                CP_ASYNC16(dst, (const char*)g_be0 + (size_t)(n0n + n) * 512 + col * 16);
            }
            CP_COMMIT();
            asm volatile("cp.async.wait_group 1;" ::: "memory");
        } else {
            asm volatile("cp.async.wait_group 0;" ::: "memory");
        }
        __syncthreads();

        uint32_t bbase = sb + (nc & 1) * DB_BYTES;
        float acc[4][2][8];
#pragma unroll
        for (int nt = 0; nt < 4; nt++)
#pragma unroll
            for (int mt = 0; mt < 2; mt++)
#pragma unroll
                for (int j = 0; j < 8; j++) acc[nt][mt][j] = 0.f;

        uint4 acur[2], anxt[2];
#pragma unroll
        for (int mt = 0; mt < 2; mt++)
            acur[mt] = *(const uint4*)(g_ax0f + abase[mt]);

#pragma unroll 1
        for (int ks = 0; ks < 16; ks++) {
            if (ks < 15) {
#pragma unroll
                for (int mt = 0; mt < 2; mt++)
                    anxt[mt] = *(const uint4*)(g_ax0f + abase[mt] + (ks + 1) * 128);
            }
#pragma unroll
            for (int nt = 0; nt < 4; nt++) {
                int nl = nt * 16 + bn;
                uint32_t baddr = bbase + nl * 512 + (((ks * 2 + bkh) ^ (nl & 7)) << 4);
                uint32_t b0, b1, b2, b3;
                LDSM_X4(b0, b1, b2, b3, baddr);
#pragma unroll
                for (int mt = 0; mt < 2; mt++) {
                    mma16816(acc[nt][mt], (const uint32_t*)&acur[mt], b0, b1);
                    mma16816(acc[nt][mt] + 4, (const uint32_t*)&acur[mt], b2, b3);
                }
            }
            acur[0] = anxt[0]; acur[1] = anxt[1];
        }

        int n0 = nc * 64;
#pragma unroll
        for (int nt = 0; nt < 4; nt++)
#pragma unroll
            for (int mt = 0; mt < 2; mt++) {
                int row0 = t0 + wid * 32 + mt * 16 + group;
#pragma unroll
                for (int nh = 0; nh < 2; nh++) {
                    int cb = n0 + nt * 16 + nh * 8 + tq * 2;
                    const float* c = &acc[nt][mt][nh * 4];
                    *(__half2*)(g_chat + (size_t)row0 * KC + cb) =
                        __floats2half2_rn(c[0], c[1]);
                    *(__half2*)(g_chat + (size_t)(row0 + 8) * KC + cb) =
                        __floats2half2_rn(c[2], c[3]);
                }
            }
        __syncthreads();
    }
}

// ---------------------------------------------------------------------------
// collect: warp per token. Reads fp16 chat row (2KB coalesced), computes
// U = min(en - 2*chat + bd) and candidates (en - 2*chat) - bd <= U + margin.
// ---------------------------------------------------------------------------
__global__ __launch_bounds__(256) void collect_kernel()
{
    __shared__ float sp[KC], sq[KC], sen[KC];
    int tid = threadIdx.x, wid = tid >> 5, lane = tid & 31;
    for (int i = tid; i < KC; i += 256) {
        sp[i] = g_p[i]; sq[i] = g_q[i]; sen[i] = g_enorm[i];
    }
    __syncthreads();

    int t = blockIdx.x * 8 + wid;
    float a = g_ta[t], b = g_tb[t];
    const __half2* ch = (const __half2*)(g_chat + (size_t)t * KC);

    __half2 v[16];
    float U = 3.4e38f;
#pragma unroll
    for (int j = 0; j < 16; j++) {
        v[j] = ch[j * 32 + lane];
        int k0 = (j * 32 + lane) * 2;
        float2 c2 = __half22float2(v[j]);
        float ch0 = sen[k0] - 2.f * c2.x;
        float ch1 = sen[k0 + 1] - 2.f * c2.y;
        float bd0 = a * sp[k0] + b * sq[k0] + SLACK;
        float bd1 = a * sp[k0 + 1] + b * sq[k0 + 1] + SLACK;
        U = fminf(U, fminf(ch0 + bd0, ch1 + bd1));
    }
#pragma unroll
    for (int off = 16; off; off >>= 1)
        U = fminf(U, __shfl_xor_sync(0xffffffffu, U, off));
    float thr = U + FP16_MARGIN;

    int cnt = 0;
    unsigned lmask = (1u << lane) - 1u;
#pragma unroll
    for (int j = 0; j < 16; j++) {
        int k0 = (j * 32 + lane) * 2;
        float2 c2 = __half22float2(v[j]);
        float ch0 = sen[k0] - 2.f * c2.x;
        float ch1 = sen[k0 + 1] - 2.f * c2.y;
        float bd0 = a * sp[k0] + b * sq[k0] + SLACK;
        float bd1 = a * sp[k0 + 1] + b * sq[k0 + 1] + SLACK;
        bool p0 = (ch0 - bd0 <= thr);
        bool p1 = (ch1 - bd1 <= thr);
        unsigned m0 = __ballot_sync(0xffffffffu, p0);
        if (p0) {
            int pos = cnt + __popc(m0 & lmask);
            if (pos < CM) g_cand[t * CM + pos] = k0;
        }
        cnt += __popc(m0);
        unsigned m1 = __ballot_sync(0xffffffffu, p1);
        if (p1) {
            int pos = cnt + __popc(m1 & lmask);
            if (pos < CM) g_cand[t * CM + pos] = k0 + 1;
        }
        cnt += __popc(m1);
    }
    if (lane == 0) g_ccnt[t] = cnt;
}

// ---------------------------------------------------------------------------
// Fused resolve + gather. Block = 32 tokens, 256 thr.
// sZ: [32][257] token-major (z rows). sE: [256][33] dim-major (embed rows).
// Phase 1: transpose-load z. Phase 2: per-warp exact argmin over candidates.
// Phase 3: gather embed rows, loss from smem-z, es atomics, z_q writes.
// ---------------------------------------------------------------------------
#define RG_SMEM ((32 * 257 + 256 * 33) * 4)

__global__ __launch_bounds__(256) void resolve_gather_kernel(
    const float* __restrict__ z, const float* __restrict__ embed,
    float* __restrict__ out)
{
    extern __shared__ float dsm[];
    float (*sZ)[257] = (float (*)[257])dsm;                 // [32][257]
    float (*sE)[33]  = (float (*)[33])(dsm + 32 * 257);     // [256][33]
    __shared__ int   kidx[32];
    __shared__ float wred[8];
    int tid = threadIdx.x, wid = tid >> 5, lane = tid & 31;
    int t0 = blockIdx.x * 32;
    int bimg = t0 >> 10, hw0 = t0 & 1023;

    // phase 1: transpose-load z (coalesced over hw)
    {
        int d0 = tid >> 5, ti = tid & 31;
#pragma unroll
        for (int mrow = 0; mrow < 32; mrow++) {
            int d = mrow * 8 + d0;
            sZ[ti][d] = z[((size_t)bimg * DDIM + d) * HW + hw0 + ti];
        }
    }
    __syncthreads();

    // phase 2: resolve 4 tokens per warp
#pragma unroll 1
    for (int it = 0; it < 4; it++) {
        int lt = wid * 4 + it;
        int t = t0 + lt;
        float x[8];
#pragma unroll
        for (int j = 0; j < 8; j++) x[j] = sZ[lt][lane * 8 + j];
        int cnt = g_ccnt[t];
        float best = 3.4e38f;
        int bk = 0;
        bool fallback = (cnt > CM) || (cnt == 0);
        int niter = fallback ? KC : cnt;
        for (int i = 0; i < niter; i++) {
            int k = fallback ? i : g_cand[t * CM + i];
            const float* er = embed + (size_t)k * DDIM + lane * 8;
            float4 e0 = *(const float4*)er;
            float4 e1 = *(const float4*)(er + 4);
            float s = x[0] * e0.x + x[1] * e0.y + x[2] * e0.z + x[3] * e0.w
                    + x[4] * e1.x + x[5] * e1.y + x[6] * e1.z + x[7] * e1.w;
#pragma unroll
            for (int off = 16; off; off >>= 1) s += __shfl_xor_sync(0xffffffffu, s, off);
            float c = g_enorm[k] - 2.f * s;
            if (c < best || (c == best && k < bk)) { best = c; bk = k; }
        }
        if (lane == 0) {
            kidx[lt] = bk;
            g_idx[t] = bk;
            out[O_IDX + t] = (float)bk;
            atomicAdd(&g_cs[bk], 1.0f);
        }
    }
    __syncthreads();

    // phase 3: gather embed rows (coalesced over dims); sE[d][token]
#pragma unroll
    for (int l = 0; l < 32; l++)
        sE[tid][l] = embed[(size_t)kidx[l] * DDIM + tid];
    __syncthreads();

    int ti = tid & 31, dq = (tid >> 5) * 4;
    int myk = kidx[ti];
    float* esrow = &g_es[(size_t)myk * DDIM];
    float lsum = 0.f;
    float* ob = out + O_ZQ + (size_t)bimg * DDIM * HW + hw0 + ti;
#pragma unroll
    for (int m = 0; m < 8; m++) {
        int d = m * 32 + dq;
        float e0 = sE[d][ti], e1 = sE[d + 1][ti], e2 = sE[d + 2][ti], e3 = sE[d + 3][ti];
        float z0 = sZ[ti][d], z1 = sZ[ti][d + 1], z2 = sZ[ti][d + 2], z3 = sZ[ti][d + 3];
        size_t zo = (size_t)d * HW;
        ob[zo] = e0; ob[zo + HW] = e1; ob[zo + 2 * HW] = e2; ob[zo + 3 * HW] = e3;
        float f0 = z0 - e0, f1 = z1 - e1, f2 = z2 - e2, f3 = z3 - e3;
        lsum += f0 * f0 + f1 * f1 + f2 * f2 + f3 * f3;
        asm volatile("red.global.add.v4.f32 [%0], {%1, %2, %3, %4};"
                     :: "l"(esrow + d), "f"(z0), "f"(z1), "f"(z2), "f"(z3) : "memory");
    }
#pragma unroll
    for (int off = 16; off; off >>= 1) lsum += __shfl_xor_sync(0xffffffffu, lsum, off);
    if ((tid & 31) == 0) wred[tid >> 5] = lsum;
    __syncthreads();
    if (tid == 0) {
        float s = 0.f;
#pragma unroll
        for (int w = 0; w < 8; w++) s += wred[w];
        g_partial[blockIdx.x] = s;
    }
}

// loss finalize + EMA cluster-size + n (single block)
__global__ void ema_a_kernel(const float* __restrict__ cluster_size,
                             float* __restrict__ out) {
    __shared__ float red[KC];
    __shared__ float red2[KC];
    int k = threadIdx.x;
    float ncs = cluster_size[k] * DECAY_F + ONE_M_DECAY * g_cs[k];
    out[O_CS + k] = ncs;
    red[k] = ncs;
    red2[k] = g_partial[k];
    __syncthreads();
    for (int off = 512; off; off >>= 1) {
        if (k < off) { red[k] += red[k + off]; red2[k] += red2[k + off]; }
        __syncthreads();
    }
    if (k == 0) { g_n = red[0]; out[O_LOSS] = red2[0] / 8388608.0f; }
}

__global__ void ema_b_kernel(const float* __restrict__ embed_avg,
                             float* __restrict__ out) {
    int idx = blockIdx.x * 256 + threadIdx.x;
    int k = idx >> 8;
    float nea = embed_avg[idx] * DECAY_F + ONE_M_DECAY * g_es[idx];
    out[O_EAVG + idx] = nea;
    float ncs = out[O_CS + k];
    float n = g_n;
    float csn = (ncs + EPS_F) / (n + KC * EPS_F) * n;
    out[O_EMB + idx] = nea / csn;
}

// ---------------------------------------------------------------------------
extern "C" void kernel_launch(void* const* d_in, const int* in_sizes, int n_in,
                              void* d_out, int out_size)
{
    const float* z            = (const float*)d_in[0];
    const float* embed        = (const float*)d_in[1];
    const float* cluster_size = (const float*)d_in[2];
    const float* embed_avg    = (const float*)d_in[3];
    float* out = (float*)d_out;

    cudaFuncSetAttribute(distA_kernel,
                         cudaFuncAttributeMaxDynamicSharedMemorySize, PA_SMEM);
    cudaFuncSetAttribute(resolve_gather_kernel,
                         cudaFuncAttributeMaxDynamicSharedMemorySize, RG_SMEM);

    void* p;
    cudaGetSymbolAddress(&p, g_es);
    cudaMemsetAsync(p, 0, KC * DDIM * sizeof(float));          // launch 1
    cudaGetSymbolAddress(&p, g_cs);
    cudaMemsetAsync(p, 0, KC * sizeof(float));                 // launch 2

    split_e_kernel<<<KC, 256>>>(embed);                        // launch 3
    split_x_kernel<<<NTOK / 32, 256>>>(z);                     // launch 4
    distA_kernel<<<NTOK / 128, 128, PA_SMEM>>>();              // launch 5
    collect_kernel<<<NTOK / 8, 256>>>();                       // launch 6 <- ncu
    resolve_gather_kernel<<<NTOK / 32, 256, RG_SMEM>>>(z, embed, out);  // launch 7
    ema_a_kernel<<<1, KC>>>(cluster_size, out);                // launch 8
    ema_b_kernel<<<KC * DDIM / 256, 256>>>(embed_avg, out);    // launch 9
}